// round 7
// baseline (speedup 1.0000x reference)
#include <cuda_runtime.h>
#include <math.h>
#include <stdint.h>

#define BSZ   32768
#define IND   256
#define NFEAT 8
#define EDIM  16
#define VOCAB 100000
#define DNUM  4

// ------------------------- scratch (device globals; no allocs) ----------
__device__ float g_gate_in[(size_t)BSZ * IND];
__device__ float g_h0[(size_t)DNUM * BSZ * 256];
__device__ float g_h1[(size_t)DNUM * BSZ * 256];
__device__ float g_g1[(size_t)DNUM * BSZ * 256];
__device__ float g_gt[(size_t)DNUM * BSZ * 256];
__device__ float g_sums3[3][2 * DNUM * 256];
__device__ float g_wrnd[1300000];                 // packed tf32 weights

// ------------------------- helpers --------------------------------------
__device__ __forceinline__ unsigned f2tf32(float x) {
    unsigned r;
    asm("cvt.rna.tf32.f32 %0, %1;" : "=r"(r) : "f"(x));
    return r;
}
__device__ __forceinline__ float roundtf(float x) { return __uint_as_float(f2tf32(x)); }

__device__ __forceinline__ void mma_tf32(float c[4], const unsigned a[4], const unsigned b[2]) {
    asm volatile(
        "mma.sync.aligned.m16n8k8.row.col.f32.tf32.tf32.f32 "
        "{%0,%1,%2,%3}, {%4,%5,%6,%7}, {%8,%9}, {%0,%1,%2,%3};"
        : "+f"(c[0]), "+f"(c[1]), "+f"(c[2]), "+f"(c[3])
        : "r"(a[0]), "r"(a[1]), "r"(a[2]), "r"(a[3]), "r"(b[0]), "r"(b[1]));
}

__device__ __forceinline__ void ldsm_x4(unsigned r[4], uint32_t addr) {
    asm volatile("ldmatrix.sync.aligned.m8n8.x4.shared.b16 {%0,%1,%2,%3}, [%4];"
                 : "=r"(r[0]), "=r"(r[1]), "=r"(r[2]), "=r"(r[3]) : "r"(addr));
}

__device__ __forceinline__ void cp16(uint32_t dst, const float* src) {
    asm volatile("cp.async.cg.shared.global [%0], [%1], 16;" :: "r"(dst), "l"(src));
}
#define CP_COMMIT() asm volatile("cp.async.commit_group;" ::: "memory")
#define CP_WAIT0()  asm volatile("cp.async.wait_group 0;" ::: "memory")

// ------------------------- weight prep: round + fragment-pack -----------
// dst float index: ((d*(K/16)+kt)*N + n)*16 + tig*4 + e,  k = 16kt + tig + 4e
struct TSeg { const float* src; float* dst; int K; int N; int total; };
struct TArgs { TSeg seg[9]; };
__global__ void prep_weights(TArgs a) {
    int s = blockIdx.y;
    int i = blockIdx.x * 256 + threadIdx.x;
    TSeg sg = a.seg[s];
    if (i >= sg.total) return;
    int KN = sg.K * sg.N;
    int d = i / KN, r = i % KN;
    int k = r / sg.N, n = r % sg.N;
    int kt = k >> 4, kr = k & 15;
    int tig = kr & 3, e = kr >> 2;
    size_t dst = ((size_t)(d * (sg.K >> 4) + kt) * sg.N + n) * 16 + tig * 4 + e;
    sg.dst[dst] = roundtf(sg.src[i]);
}

// ------------------------- embedding gather (+ zero sums) ---------------
__global__ void embed_kernel(const int* __restrict__ id_idx,
                             const int* __restrict__ agn_idx,
                             const float* __restrict__ id_tab,
                             const float* __restrict__ agn_tab) {
    int t = blockIdx.x * blockDim.x + threadIdx.x;
    if (t < 3 * 2 * DNUM * 256) ((float*)g_sums3)[t] = 0.0f;
    if (t >= BSZ * 64) return;
    int b = t >> 6;
    int j = (t & 63) << 2;
    const int*   idx = id_idx;
    const float* tab = id_tab;
    int jj = j;
    if (j >= 128) { idx = agn_idx; tab = agn_tab; jj = j - 128; }
    int f = jj >> 4, e = jj & 15;
    int v = idx[b * NFEAT + f];
    float4 val = *(const float4*)(tab + ((size_t)f * VOCAB + v) * EDIM + e);
    val.x = roundtf(val.x); val.y = roundtf(val.y);
    val.z = roundtf(val.z); val.w = roundtf(val.w);
    *(float4*)(g_gate_in + (size_t)b * IND + j) = val;
}

// ------------------------- tensor-core GEMM ------------------------------
// C[d] = A[d] (BSZ x K, tf32-rounded) @ W(packed)[d] + bias[d]
// EPI: 0 = none + column stats, 1 = relu+round, 2 = 2*sigmoid
// BM=64, BK=16, 256 threads = 8 warps (2m x 4n). Warp tile 32 x (BN/4).
// A frags via ldmatrix.x4, B frags via packed LDS.128.
template <int BN, int EPI>
__global__ void __launch_bounds__(256, 3)
gemm_tc(const float* __restrict__ A, size_t aDomStride,
        const float* __restrict__ Wp,
        const float* __restrict__ bias,
        float* __restrict__ C,
        float* __restrict__ sums,
        int K, int N) {
    constexpr int BM = 64, BK = 16;
    constexpr int WN = BN / 4;               // 32 or 16
    constexpr int NI = WN / 8;               // 4 or 2
    constexpr int APAD = 20;
    constexpr int ABYTES = BM * APAD * 4;    // 5120
    constexpr int BQ = BN * 4;               // float4 quads per B chunk

    __shared__ __align__(16) float As[2][BM][APAD];
    __shared__ __align__(16) float Bs[2][BN * 16];
    __shared__ float cs[BN], cq[BN];

    int d  = blockIdx.z;
    int bm = blockIdx.x * BM;
    int bn = blockIdx.y * BN;
    const float* Ad = A + (size_t)d * aDomStride + (size_t)bm * K;
    const float* Bd = Wp + (size_t)d * K * N + (size_t)bn * 16;
    float*       Cd = C + ((size_t)d * BSZ + bm) * N + bn;

    int tid  = threadIdx.x;
    int lane = tid & 31, wid = tid >> 5;
    int gid  = lane >> 2, tig = lane & 3;
    int wm   = wid >> 2,  wn  = wid & 3;

    int arow = tid >> 2, akc = (tid & 3) << 2;     // A: 64 rows x 16k, 1 cp16/thread

    const float* Aptr = Ad + (size_t)arow * K + akc;

    uint32_t sA = (uint32_t)__cvta_generic_to_shared(&As[0][0][0]);
    uint32_t sB = (uint32_t)__cvta_generic_to_shared(&Bs[0][0]);

    // ldmatrix per-lane address base: row = wm*32 + (lane&15), col = (lane>>4)*4
    uint32_t lrow = lane & 15;
    uint32_t lcol = (lane >> 4) << 2;
    uint32_t aFragBase = sA + (((wm * 32 + lrow) * APAD + lcol) << 2);

    float acc[2][NI][4] = {};

    auto stage = [&](int kt, int st) {
        cp16(sA + (((st * BM + arow) * APAD + akc) << 2), Aptr + kt * 16);
        const float* Bq = Bd + (size_t)kt * N * 16;
#pragma unroll
        for (int i = 0; i < BQ / 256; i++) {
            int q = tid + i * 256;
            cp16(sB + ((st * BN * 16 + q * 4) << 2), Bq + q * 4);
        }
        CP_COMMIT();
    };

    const int NCH = K / BK;
    stage(0, 0);

    int s = 0;
    for (int c = 0; c < NCH; c++) {
        CP_WAIT0();
        __syncthreads();

        if (c + 1 < NCH) stage(c + 1, s ^ 1);

        uint32_t aS = aFragBase + (s ? ABYTES : 0);

        // B fragments: one LDS.128 per ni (covers both k-halves)
        float4 bq[NI];
#pragma unroll
        for (int ni = 0; ni < NI; ni++) {
            int cb = wn * WN + ni * 8 + gid;
            bq[ni] = *(const float4*)&Bs[s][cb * 16 + tig * 4];
        }

        // A fragments: ldmatrix.x4 per mi covers k 0..7; second for k 8..15
#pragma unroll
        for (int ks = 0; ks < 2; ks++) {
            unsigned af[2][4];
            ldsm_x4(af[0], aS + ks * 32);
            ldsm_x4(af[1], aS + ks * 32 + 16 * APAD * 4);
#pragma unroll
            for (int mi = 0; mi < 2; mi++)
#pragma unroll
                for (int ni = 0; ni < NI; ni++) {
                    unsigned b2[2];
                    if (ks == 0) { b2[0] = __float_as_uint(bq[ni].x); b2[1] = __float_as_uint(bq[ni].y); }
                    else         { b2[0] = __float_as_uint(bq[ni].z); b2[1] = __float_as_uint(bq[ni].w); }
                    mma_tf32(acc[mi][ni], af[mi], b2);
                }
        }
        s ^= 1;
    }

    if (EPI == 0) {
        if (tid < BN) { cs[tid] = 0.0f; cq[tid] = 0.0f; }
        __syncthreads();
    }

    float colS[NI][2] = {}, colQ[NI][2] = {};

#pragma unroll
    for (int mi = 0; mi < 2; mi++) {
        int r0 = wm * 32 + mi * 16 + gid;
#pragma unroll
        for (int ni = 0; ni < NI; ni++) {
            int col = wn * WN + ni * 8 + 2 * tig;
            float b0 = bias[d * N + bn + col];
            float b1 = bias[d * N + bn + col + 1];
            float v0 = acc[mi][ni][0] + b0;
            float v1 = acc[mi][ni][1] + b1;
            float v2 = acc[mi][ni][2] + b0;
            float v3 = acc[mi][ni][3] + b1;
            if (EPI == 1) {
                v0 = roundtf(fmaxf(v0, 0.0f)); v1 = roundtf(fmaxf(v1, 0.0f));
                v2 = roundtf(fmaxf(v2, 0.0f)); v3 = roundtf(fmaxf(v3, 0.0f));
            }
            if (EPI == 2) {
                v0 = 2.0f / (1.0f + expf(-v0)); v1 = 2.0f / (1.0f + expf(-v1));
                v2 = 2.0f / (1.0f + expf(-v2)); v3 = 2.0f / (1.0f + expf(-v3));
            }
            if (EPI == 0) {
                colS[ni][0] += v0 + v2;      colS[ni][1] += v1 + v3;
                colQ[ni][0] += v0 * v0 + v2 * v2;
                colQ[ni][1] += v1 * v1 + v3 * v3;
            }
            *(float2*)(Cd + (size_t)r0 * N + col)       = make_float2(v0, v1);
            *(float2*)(Cd + (size_t)(r0 + 8) * N + col) = make_float2(v2, v3);
        }
    }

    if (EPI == 0) {
#pragma unroll
        for (int ni = 0; ni < NI; ni++)
#pragma unroll
            for (int c2 = 0; c2 < 2; c2++) {
                float sv = colS[ni][c2], qv = colQ[ni][c2];
                sv += __shfl_xor_sync(0xffffffffu, sv, 16);
                sv += __shfl_xor_sync(0xffffffffu, sv, 8);
                sv += __shfl_xor_sync(0xffffffffu, sv, 4);
                qv += __shfl_xor_sync(0xffffffffu, qv, 16);
                qv += __shfl_xor_sync(0xffffffffu, qv, 8);
                qv += __shfl_xor_sync(0xffffffffu, qv, 4);
                if (gid == 0) {
                    int c = wn * WN + ni * 8 + 2 * tig + c2;
                    atomicAdd(&cs[c], sv);
                    atomicAdd(&cq[c], qv);
                }
            }
        __syncthreads();
        if (tid < BN) {
            atomicAdd(&sums[d * 256 + bn + tid], cs[tid]);
            atomicAdd(&sums[DNUM * 256 + d * 256 + bn + tid], cq[tid]);
        }
    }
}

// ------------------------- BN apply + gate ------------------------------
__global__ void bn_apply_gate(float* __restrict__ H, const float* __restrict__ G,
                              const float* __restrict__ sums,
                              const float* __restrict__ bng,
                              const float* __restrict__ bnb, int N) {
    size_t t = (size_t)blockIdx.x * blockDim.x + threadIdx.x;
    size_t total4 = (size_t)DNUM * BSZ * N / 4;
    if (t >= total4) return;
    size_t e = t * 4;
    int c = (int)(e % N);
    int d = (int)(e / ((size_t)BSZ * N));
    float4 h = *(float4*)(H + e);
    float4 g = *(const float4*)(G + e);
    float r[4] = {h.x, h.y, h.z, h.w};
    float gg[4] = {g.x, g.y, g.z, g.w};
#pragma unroll
    for (int j = 0; j < 4; j++) {
        int idx = d * 256 + c + j;
        float mean = sums[idx] * (1.0f / BSZ);
        float var  = sums[DNUM * 256 + idx] * (1.0f / BSZ) - mean * mean;
        float sc   = bng[d * N + c + j] * rsqrtf(var + 1e-5f);
        float sh   = bnb[d * N + c + j] - mean * sc;
        r[j] = roundtf(fmaxf(r[j] * sc + sh, 0.0f) * gg[j]);
    }
    *(float4*)(H + e) = make_float4(r[0], r[1], r[2], r[3]);
}

// ------------------------- final head -----------------------------------
__global__ void final_kernel(const float* __restrict__ H,
                             const int* __restrict__ dom,
                             const float* __restrict__ finW,
                             const float* __restrict__ finb,
                             float* __restrict__ out) {
    int warp = (blockIdx.x * blockDim.x + threadIdx.x) >> 5;
    int lane = threadIdx.x & 31;
    if (warp >= BSZ) return;
    int d = dom[warp];
    const float* h = H + ((size_t)d * BSZ + warp) * 64;
    const float* w = finW + d * 64;
    float s = h[lane] * w[lane] + h[lane + 32] * w[lane + 32];
#pragma unroll
    for (int o = 16; o > 0; o >>= 1) s += __shfl_down_sync(0xffffffffu, s, o);
    if (lane == 0) out[warp] = 1.0f / (1.0f + expf(-(s + finb[d])));
}

// ------------------------- dispatch helper ------------------------------
template <int EPI>
static void launch_gemm(const float* A, size_t aStride, const float* Wp,
                        const float* b, float* C, float* sums, int K, int N) {
    if (N >= 128) {
        dim3 grid(BSZ / 64, N / 128, DNUM);
        gemm_tc<128, EPI><<<grid, 256>>>(A, aStride, Wp, b, C, sums, K, N);
    } else {
        dim3 grid(BSZ / 64, N / 64, DNUM);
        gemm_tc<64, EPI><<<grid, 256>>>(A, aStride, Wp, b, C, sums, K, N);
    }
}

// ------------------------- launch --------------------------------------
extern "C" void kernel_launch(void* const* d_in, const int* in_sizes, int n_in,
                              void* d_out, int out_size) {
    const int*   id_idx    = (const int*)d_in[0];
    const int*   agn_idx   = (const int*)d_in[1];
    const int*   domain_id = (const int*)d_in[2];
    const float* id_tab    = (const float*)d_in[3];
    const float* agn_tab   = (const float*)d_in[4];
    const float* mlp_W[3]  = {(const float*)d_in[5],  (const float*)d_in[13], (const float*)d_in[21]};
    const float* mlp_b[3]  = {(const float*)d_in[6],  (const float*)d_in[14], (const float*)d_in[22]};
    const float* bn_g[3]   = {(const float*)d_in[7],  (const float*)d_in[15], (const float*)d_in[23]};
    const float* bn_b[3]   = {(const float*)d_in[8],  (const float*)d_in[16], (const float*)d_in[24]};
    const float* gW1[3]    = {(const float*)d_in[9],  (const float*)d_in[17], (const float*)d_in[25]};
    const float* gb1[3]    = {(const float*)d_in[10], (const float*)d_in[18], (const float*)d_in[26]};
    const float* gW2[3]    = {(const float*)d_in[11], (const float*)d_in[19], (const float*)d_in[27]};
    const float* gb2[3]    = {(const float*)d_in[12], (const float*)d_in[20], (const float*)d_in[28]};
    const float* finW      = (const float*)d_in[29];
    const float* finb      = (const float*)d_in[30];
    float*       out       = (float*)d_out;

    float *p_gate_in, *p_h0, *p_h1, *p_g1, *p_gt, *p_sums, *p_w;
    cudaGetSymbolAddress((void**)&p_gate_in, g_gate_in);
    cudaGetSymbolAddress((void**)&p_h0, g_h0);
    cudaGetSymbolAddress((void**)&p_h1, g_h1);
    cudaGetSymbolAddress((void**)&p_g1, g_g1);
    cudaGetSymbolAddress((void**)&p_gt, g_gt);
    cudaGetSymbolAddress((void**)&p_sums, g_sums3);
    cudaGetSymbolAddress((void**)&p_w, g_wrnd);

    const int dims[4] = {256, 256, 128, 64};

    // packed weights
    float* rW1[3]; float* rW2[3]; float* rWm[3];
    size_t off = 0;
    TArgs ta;
    int segi = 0, maxn = 0;
    for (int i = 0; i < 3; i++) {
        int N = dims[i + 1];
        rW1[i] = p_w + off;
        ta.seg[segi++] = {gW1[i], p_w + off, IND, N, DNUM * IND * N};           off += (size_t)DNUM * IND * N;
        rW2[i] = p_w + off;
        ta.seg[segi++] = {gW2[i], p_w + off, N, N, DNUM * N * N};               off += (size_t)DNUM * N * N;
        rWm[i] = p_w + off;
        ta.seg[segi++] = {mlp_W[i], p_w + off, dims[i], N, DNUM * dims[i] * N}; off += (size_t)DNUM * dims[i] * N;
    }
    for (int s = 0; s < 9; s++) if (ta.seg[s].total > maxn) maxn = ta.seg[s].total;

    dim3 rg((maxn + 255) / 256, 9);
    prep_weights<<<rg, 256>>>(ta);

    embed_kernel<<<(BSZ * 64 + 255) / 256, 256>>>(id_idx, agn_idx, id_tab, agn_tab);

    float* hbuf[2] = {p_h0, p_h1};
    const float* hprev = nullptr;

    for (int i = 0; i < 3; i++) {
        int Kmlp = dims[i];
        int N    = dims[i + 1];
        float* hout = hbuf[i & 1];
        float* sums = p_sums + (size_t)i * 2 * DNUM * 256;

        launch_gemm<1>(p_gate_in, 0, rW1[i], gb1[i], p_g1, nullptr, IND, N);
        launch_gemm<2>(p_g1, (size_t)BSZ * N, rW2[i], gb2[i], p_gt, nullptr, N, N);
        if (i == 0)
            launch_gemm<0>(p_gate_in, 0, rWm[i], mlp_b[i], hout, sums, IND, N);
        else
            launch_gemm<0>(hprev, (size_t)BSZ * Kmlp, rWm[i], mlp_b[i], hout, sums, Kmlp, N);

        size_t tot4 = (size_t)DNUM * BSZ * N / 4;
        bn_apply_gate<<<(unsigned)((tot4 + 255) / 256), 256>>>(hout, p_gt, sums, bn_g[i], bn_b[i], N);

        hprev = hout;
    }

    final_kernel<<<BSZ / 8, 256>>>(hprev, domain_id, finW, finb, out);
}

// round 8
// speedup vs baseline: 1.4869x; 1.4869x over previous
#include <cuda_runtime.h>
#include <math.h>
#include <stdint.h>

#define BSZ   32768
#define IND   256
#define NFEAT 8
#define EDIM  16
#define VOCAB 100000
#define DNUM  4

// ------------------------- scratch (device globals; no allocs) ----------
__device__ float g_gate_in[(size_t)BSZ * IND];
__device__ float g_h0[(size_t)DNUM * BSZ * 256];
__device__ float g_h1[(size_t)DNUM * BSZ * 256];
__device__ float g_g1[(size_t)DNUM * BSZ * 256];
__device__ float g_gt[(size_t)DNUM * BSZ * 256];
__device__ float g_sums3[3][2 * DNUM * 256];
__device__ float g_wrnd[1300000];                 // packed tf32 weights

// ------------------------- helpers --------------------------------------
__device__ __forceinline__ unsigned f2tf32(float x) {
    unsigned r;
    asm("cvt.rna.tf32.f32 %0, %1;" : "=r"(r) : "f"(x));
    return r;
}
__device__ __forceinline__ float roundtf(float x) { return __uint_as_float(f2tf32(x)); }

__device__ __forceinline__ void mma_tf32(float c[4], const unsigned a[4], const unsigned b[2]) {
    asm volatile(
        "mma.sync.aligned.m16n8k8.row.col.f32.tf32.tf32.f32 "
        "{%0,%1,%2,%3}, {%4,%5,%6,%7}, {%8,%9}, {%0,%1,%2,%3};"
        : "+f"(c[0]), "+f"(c[1]), "+f"(c[2]), "+f"(c[3])
        : "r"(a[0]), "r"(a[1]), "r"(a[2]), "r"(a[3]), "r"(b[0]), "r"(b[1]));
}

__device__ __forceinline__ void ldsm_x4(unsigned r[4], uint32_t addr) {
    asm volatile("ldmatrix.sync.aligned.m8n8.x4.shared.b16 {%0,%1,%2,%3}, [%4];"
                 : "=r"(r[0]), "=r"(r[1]), "=r"(r[2]), "=r"(r[3]) : "r"(addr));
}

__device__ __forceinline__ void cp16(uint32_t dst, const float* src) {
    asm volatile("cp.async.cg.shared.global [%0], [%1], 16;" :: "r"(dst), "l"(src));
}
#define CP_COMMIT() asm volatile("cp.async.commit_group;" ::: "memory")
#define CP_WAIT0()  asm volatile("cp.async.wait_group 0;" ::: "memory")

// ------------------------- weight prep: round + fragment-pack -----------
// dst float index: ((d*(K/16)+kt)*N + n)*16 + tig*4 + e,  k = 16kt + tig + 4e
struct TSeg { const float* src; float* dst; int K; int N; int total; };
struct TArgs { TSeg seg[9]; };
__global__ void prep_weights(TArgs a) {
    int s = blockIdx.y;
    int i = blockIdx.x * 256 + threadIdx.x;
    TSeg sg = a.seg[s];
    if (i >= sg.total) return;
    int KN = sg.K * sg.N;
    int d = i / KN, r = i % KN;
    int k = r / sg.N, n = r % sg.N;
    int kt = k >> 4, kr = k & 15;
    int tig = kr & 3, e = kr >> 2;
    size_t dst = ((size_t)(d * (sg.K >> 4) + kt) * sg.N + n) * 16 + tig * 4 + e;
    sg.dst[dst] = roundtf(sg.src[i]);
}

// ------------------------- embedding gather (+ zero sums) ---------------
__global__ void embed_kernel(const int* __restrict__ id_idx,
                             const int* __restrict__ agn_idx,
                             const float* __restrict__ id_tab,
                             const float* __restrict__ agn_tab) {
    int t = blockIdx.x * blockDim.x + threadIdx.x;
    if (t < 3 * 2 * DNUM * 256) ((float*)g_sums3)[t] = 0.0f;
    if (t >= BSZ * 64) return;
    int b = t >> 6;
    int j = (t & 63) << 2;
    const int*   idx = id_idx;
    const float* tab = id_tab;
    int jj = j;
    if (j >= 128) { idx = agn_idx; tab = agn_tab; jj = j - 128; }
    int f = jj >> 4, e = jj & 15;
    int v = idx[b * NFEAT + f];
    float4 val = *(const float4*)(tab + ((size_t)f * VOCAB + v) * EDIM + e);
    val.x = roundtf(val.x); val.y = roundtf(val.y);
    val.z = roundtf(val.z); val.w = roundtf(val.w);
    *(float4*)(g_gate_in + (size_t)b * IND + j) = val;
}

// ------------------------- tensor-core GEMM ------------------------------
// C[d] = A[d] (BSZ x K, tf32-rounded) @ W(packed)[d] + bias[d]
// EPI: 0 = none + column stats, 1 = relu+round, 2 = 2*sigmoid
// BM=128, BK=16. 8 warps (4m x 2n). Warp tile 32 x (BN/2).
// A frags via ldmatrix.x4, B frags via packed LDS.128.
template <int BN, int EPI>
__global__ void __launch_bounds__(256, 2)
gemm_tc(const float* __restrict__ A, size_t aDomStride,
        const float* __restrict__ Wp,
        const float* __restrict__ bias,
        float* __restrict__ C,
        float* __restrict__ sums,
        int K, int N) {
    constexpr int BM = 128, BK = 16;
    constexpr int WN = BN / 2;               // 64 or 32
    constexpr int NI = WN / 8;               // 8 or 4
    constexpr int APAD = 20;
    constexpr int ABYTES = BM * APAD * 4;    // 10240
    constexpr int BQ = BN * 4;               // float4 quads per B chunk

    __shared__ __align__(16) float As[2][BM][APAD];
    __shared__ __align__(16) float Bs[2][BN * 16];
    __shared__ float cs[BN], cq[BN];

    int d  = blockIdx.z;
    int bm = blockIdx.x * BM;
    int bn = blockIdx.y * BN;
    const float* Ad = A + (size_t)d * aDomStride + (size_t)bm * K;
    const float* Bd = Wp + (size_t)d * K * N + (size_t)bn * 16;
    float*       Cd = C + ((size_t)d * BSZ + bm) * N + bn;

    int tid  = threadIdx.x;
    int lane = tid & 31, wid = tid >> 5;
    int gid  = lane >> 2, tig = lane & 3;
    int wm   = wid >> 1,  wn  = wid & 1;

    int arow = tid >> 2, akc = (tid & 3) << 2;     // A: 64 rows x 16k, two row groups

    const float* Aptr0 = Ad + (size_t)arow * K + akc;
    const float* Aptr1 = Ad + (size_t)(arow + 64) * K + akc;

    uint32_t sA = (uint32_t)__cvta_generic_to_shared(&As[0][0][0]);
    uint32_t sB = (uint32_t)__cvta_generic_to_shared(&Bs[0][0]);

    // ldmatrix lane addressing: rows = warp m-base + (lane&15), col = (lane>>4)*4
    uint32_t lrow = lane & 15;
    uint32_t lcol = (lane >> 4) << 2;
    uint32_t aFragBase = sA + (((wm * 32 + lrow) * APAD + lcol) << 2);

    float acc[2][NI][4] = {};

    auto stage = [&](int kt, int st) {
        cp16(sA + (((st * BM + arow) * APAD + akc) << 2), Aptr0 + kt * 16);
        cp16(sA + (((st * BM + arow + 64) * APAD + akc) << 2), Aptr1 + kt * 16);
        const float* Bq = Bd + (size_t)kt * N * 16;
#pragma unroll
        for (int i = 0; i < BQ / 256; i++) {
            int q = tid + i * 256;
            cp16(sB + ((st * BN * 16 + q * 4) << 2), Bq + q * 4);
        }
        CP_COMMIT();
    };

    const int NCH = K / BK;
    stage(0, 0);

    int s = 0;
    for (int c = 0; c < NCH; c++) {
        CP_WAIT0();
        __syncthreads();

        if (c + 1 < NCH) stage(c + 1, s ^ 1);

        uint32_t aS = aFragBase + (s ? ABYTES : 0);

        // B fragments: one LDS.128 per ni (covers both k-halves)
        float4 bq[NI];
#pragma unroll
        for (int ni = 0; ni < NI; ni++) {
            int cb = wn * WN + ni * 8 + gid;
            bq[ni] = *(const float4*)&Bs[s][cb * 16 + tig * 4];
        }

        // A fragments: 2 x ldmatrix.x4 per k-half (mi = 0, 1)
#pragma unroll
        for (int ks = 0; ks < 2; ks++) {
            unsigned af[2][4];
            ldsm_x4(af[0], aS + ks * 32);
            ldsm_x4(af[1], aS + ks * 32 + 16 * APAD * 4);
#pragma unroll
            for (int mi = 0; mi < 2; mi++)
#pragma unroll
                for (int ni = 0; ni < NI; ni++) {
                    unsigned b2[2];
                    if (ks == 0) { b2[0] = __float_as_uint(bq[ni].x); b2[1] = __float_as_uint(bq[ni].y); }
                    else         { b2[0] = __float_as_uint(bq[ni].z); b2[1] = __float_as_uint(bq[ni].w); }
                    mma_tf32(acc[mi][ni], af[mi], b2);
                }
        }
        s ^= 1;
    }

    if (EPI == 0) {
        if (tid < BN) { cs[tid] = 0.0f; cq[tid] = 0.0f; }
        __syncthreads();
    }

    float colS[NI][2] = {}, colQ[NI][2] = {};

#pragma unroll
    for (int mi = 0; mi < 2; mi++) {
        int r0 = wm * 32 + mi * 16 + gid;
#pragma unroll
        for (int ni = 0; ni < NI; ni++) {
            int col = wn * WN + ni * 8 + 2 * tig;
            float b0 = bias[d * N + bn + col];
            float b1 = bias[d * N + bn + col + 1];
            float v0 = acc[mi][ni][0] + b0;
            float v1 = acc[mi][ni][1] + b1;
            float v2 = acc[mi][ni][2] + b0;
            float v3 = acc[mi][ni][3] + b1;
            if (EPI == 1) {
                v0 = roundtf(fmaxf(v0, 0.0f)); v1 = roundtf(fmaxf(v1, 0.0f));
                v2 = roundtf(fmaxf(v2, 0.0f)); v3 = roundtf(fmaxf(v3, 0.0f));
            }
            if (EPI == 2) {
                v0 = 2.0f / (1.0f + expf(-v0)); v1 = 2.0f / (1.0f + expf(-v1));
                v2 = 2.0f / (1.0f + expf(-v2)); v3 = 2.0f / (1.0f + expf(-v3));
            }
            if (EPI == 0) {
                colS[ni][0] += v0 + v2;      colS[ni][1] += v1 + v3;
                colQ[ni][0] += v0 * v0 + v2 * v2;
                colQ[ni][1] += v1 * v1 + v3 * v3;
            }
            *(float2*)(Cd + (size_t)r0 * N + col)       = make_float2(v0, v1);
            *(float2*)(Cd + (size_t)(r0 + 8) * N + col) = make_float2(v2, v3);
        }
    }

    if (EPI == 0) {
#pragma unroll
        for (int ni = 0; ni < NI; ni++)
#pragma unroll
            for (int c2 = 0; c2 < 2; c2++) {
                float sv = colS[ni][c2], qv = colQ[ni][c2];
                sv += __shfl_xor_sync(0xffffffffu, sv, 16);
                sv += __shfl_xor_sync(0xffffffffu, sv, 8);
                sv += __shfl_xor_sync(0xffffffffu, sv, 4);
                qv += __shfl_xor_sync(0xffffffffu, qv, 16);
                qv += __shfl_xor_sync(0xffffffffu, qv, 8);
                qv += __shfl_xor_sync(0xffffffffu, qv, 4);
                if (gid == 0) {
                    int c = wn * WN + ni * 8 + 2 * tig + c2;
                    atomicAdd(&cs[c], sv);
                    atomicAdd(&cq[c], qv);
                }
            }
        __syncthreads();
        if (tid < BN) {
            atomicAdd(&sums[d * 256 + bn + tid], cs[tid]);
            atomicAdd(&sums[DNUM * 256 + d * 256 + bn + tid], cq[tid]);
        }
    }
}

// ------------------------- BN apply + gate ------------------------------
__global__ void bn_apply_gate(float* __restrict__ H, const float* __restrict__ G,
                              const float* __restrict__ sums,
                              const float* __restrict__ bng,
                              const float* __restrict__ bnb, int N) {
    size_t t = (size_t)blockIdx.x * blockDim.x + threadIdx.x;
    size_t total4 = (size_t)DNUM * BSZ * N / 4;
    if (t >= total4) return;
    size_t e = t * 4;
    int c = (int)(e % N);
    int d = (int)(e / ((size_t)BSZ * N));
    float4 h = *(float4*)(H + e);
    float4 g = *(const float4*)(G + e);
    float r[4] = {h.x, h.y, h.z, h.w};
    float gg[4] = {g.x, g.y, g.z, g.w};
#pragma unroll
    for (int j = 0; j < 4; j++) {
        int idx = d * 256 + c + j;
        float mean = sums[idx] * (1.0f / BSZ);
        float var  = sums[DNUM * 256 + idx] * (1.0f / BSZ) - mean * mean;
        float sc   = bng[d * N + c + j] * rsqrtf(var + 1e-5f);
        float sh   = bnb[d * N + c + j] - mean * sc;
        r[j] = roundtf(fmaxf(r[j] * sc + sh, 0.0f) * gg[j]);
    }
    *(float4*)(H + e) = make_float4(r[0], r[1], r[2], r[3]);
}

// ------------------------- final head -----------------------------------
__global__ void final_kernel(const float* __restrict__ H,
                             const int* __restrict__ dom,
                             const float* __restrict__ finW,
                             const float* __restrict__ finb,
                             float* __restrict__ out) {
    int warp = (blockIdx.x * blockDim.x + threadIdx.x) >> 5;
    int lane = threadIdx.x & 31;
    if (warp >= BSZ) return;
    int d = dom[warp];
    const float* h = H + ((size_t)d * BSZ + warp) * 64;
    const float* w = finW + d * 64;
    float s = h[lane] * w[lane] + h[lane + 32] * w[lane + 32];
#pragma unroll
    for (int o = 16; o > 0; o >>= 1) s += __shfl_down_sync(0xffffffffu, s, o);
    if (lane == 0) out[warp] = 1.0f / (1.0f + expf(-(s + finb[d])));
}

// ------------------------- dispatch helper ------------------------------
template <int EPI>
static void launch_gemm(const float* A, size_t aStride, const float* Wp,
                        const float* b, float* C, float* sums, int K, int N) {
    if (N >= 128) {
        dim3 grid(BSZ / 128, N / 128, DNUM);
        gemm_tc<128, EPI><<<grid, 256>>>(A, aStride, Wp, b, C, sums, K, N);
    } else {
        dim3 grid(BSZ / 128, N / 64, DNUM);
        gemm_tc<64, EPI><<<grid, 256>>>(A, aStride, Wp, b, C, sums, K, N);
    }
}

// ------------------------- launch --------------------------------------
extern "C" void kernel_launch(void* const* d_in, const int* in_sizes, int n_in,
                              void* d_out, int out_size) {
    const int*   id_idx    = (const int*)d_in[0];
    const int*   agn_idx   = (const int*)d_in[1];
    const int*   domain_id = (const int*)d_in[2];
    const float* id_tab    = (const float*)d_in[3];
    const float* agn_tab   = (const float*)d_in[4];
    const float* mlp_W[3]  = {(const float*)d_in[5],  (const float*)d_in[13], (const float*)d_in[21]};
    const float* mlp_b[3]  = {(const float*)d_in[6],  (const float*)d_in[14], (const float*)d_in[22]};
    const float* bn_g[3]   = {(const float*)d_in[7],  (const float*)d_in[15], (const float*)d_in[23]};
    const float* bn_b[3]   = {(const float*)d_in[8],  (const float*)d_in[16], (const float*)d_in[24]};
    const float* gW1[3]    = {(const float*)d_in[9],  (const float*)d_in[17], (const float*)d_in[25]};
    const float* gb1[3]    = {(const float*)d_in[10], (const float*)d_in[18], (const float*)d_in[26]};
    const float* gW2[3]    = {(const float*)d_in[11], (const float*)d_in[19], (const float*)d_in[27]};
    const float* gb2[3]    = {(const float*)d_in[12], (const float*)d_in[20], (const float*)d_in[28]};
    const float* finW      = (const float*)d_in[29];
    const float* finb      = (const float*)d_in[30];
    float*       out       = (float*)d_out;

    float *p_gate_in, *p_h0, *p_h1, *p_g1, *p_gt, *p_sums, *p_w;
    cudaGetSymbolAddress((void**)&p_gate_in, g_gate_in);
    cudaGetSymbolAddress((void**)&p_h0, g_h0);
    cudaGetSymbolAddress((void**)&p_h1, g_h1);
    cudaGetSymbolAddress((void**)&p_g1, g_g1);
    cudaGetSymbolAddress((void**)&p_gt, g_gt);
    cudaGetSymbolAddress((void**)&p_sums, g_sums3);
    cudaGetSymbolAddress((void**)&p_w, g_wrnd);

    const int dims[4] = {256, 256, 128, 64};

    // packed weights
    float* rW1[3]; float* rW2[3]; float* rWm[3];
    size_t off = 0;
    TArgs ta;
    int segi = 0, maxn = 0;
    for (int i = 0; i < 3; i++) {
        int N = dims[i + 1];
        rW1[i] = p_w + off;
        ta.seg[segi++] = {gW1[i], p_w + off, IND, N, DNUM * IND * N};           off += (size_t)DNUM * IND * N;
        rW2[i] = p_w + off;
        ta.seg[segi++] = {gW2[i], p_w + off, N, N, DNUM * N * N};               off += (size_t)DNUM * N * N;
        rWm[i] = p_w + off;
        ta.seg[segi++] = {mlp_W[i], p_w + off, dims[i], N, DNUM * dims[i] * N}; off += (size_t)DNUM * dims[i] * N;
    }
    for (int s = 0; s < 9; s++) if (ta.seg[s].total > maxn) maxn = ta.seg[s].total;

    dim3 rg((maxn + 255) / 256, 9);
    prep_weights<<<rg, 256>>>(ta);

    embed_kernel<<<(BSZ * 64 + 255) / 256, 256>>>(id_idx, agn_idx, id_tab, agn_tab);

    float* hbuf[2] = {p_h0, p_h1};
    const float* hprev = nullptr;

    for (int i = 0; i < 3; i++) {
        int Kmlp = dims[i];
        int N    = dims[i + 1];
        float* hout = hbuf[i & 1];
        float* sums = p_sums + (size_t)i * 2 * DNUM * 256;

        launch_gemm<1>(p_gate_in, 0, rW1[i], gb1[i], p_g1, nullptr, IND, N);
        launch_gemm<2>(p_g1, (size_t)BSZ * N, rW2[i], gb2[i], p_gt, nullptr, N, N);
        if (i == 0)
            launch_gemm<0>(p_gate_in, 0, rWm[i], mlp_b[i], hout, sums, IND, N);
        else
            launch_gemm<0>(hprev, (size_t)BSZ * Kmlp, rWm[i], mlp_b[i], hout, sums, Kmlp, N);

        size_t tot4 = (size_t)DNUM * BSZ * N / 4;
        bn_apply_gate<<<(unsigned)((tot4 + 255) / 256), 256>>>(hout, p_gt, sums, bn_g[i], bn_b[i], N);

        hprev = hout;
    }

    final_kernel<<<BSZ / 8, 256>>>(hprev, domain_id, finW, finb, out);
}

// round 9
// speedup vs baseline: 1.6245x; 1.0926x over previous
#include <cuda_runtime.h>
#include <math.h>
#include <stdint.h>

#define BSZ   32768
#define IND   256
#define NFEAT 8
#define EDIM  16
#define VOCAB 100000
#define DNUM  4

// ------------------------- scratch (device globals; no allocs) ----------
__device__ float g_gate_in[(size_t)BSZ * IND];
__device__ float g_h0[(size_t)DNUM * BSZ * 256];
__device__ float g_h1[(size_t)DNUM * BSZ * 256];
__device__ float g_g1[(size_t)DNUM * BSZ * 256];
__device__ float g_gt[(size_t)DNUM * BSZ * 256];
__device__ float g_sums3[3][2 * DNUM * 256];
__device__ float g_wrnd[1300000];                 // packed tf32 weights

// ------------------------- helpers --------------------------------------
__device__ __forceinline__ unsigned f2tf32(float x) {
    unsigned r;
    asm("cvt.rna.tf32.f32 %0, %1;" : "=r"(r) : "f"(x));
    return r;
}
__device__ __forceinline__ float roundtf(float x) { return __uint_as_float(f2tf32(x)); }

__device__ __forceinline__ void mma_tf32(float c[4], const unsigned a[4], const unsigned b[2]) {
    asm volatile(
        "mma.sync.aligned.m16n8k8.row.col.f32.tf32.tf32.f32 "
        "{%0,%1,%2,%3}, {%4,%5,%6,%7}, {%8,%9}, {%0,%1,%2,%3};"
        : "+f"(c[0]), "+f"(c[1]), "+f"(c[2]), "+f"(c[3])
        : "r"(a[0]), "r"(a[1]), "r"(a[2]), "r"(a[3]), "r"(b[0]), "r"(b[1]));
}

__device__ __forceinline__ void ldsm_x4(unsigned r[4], uint32_t addr) {
    asm volatile("ldmatrix.sync.aligned.m8n8.x4.shared.b16 {%0,%1,%2,%3}, [%4];"
                 : "=r"(r[0]), "=r"(r[1]), "=r"(r[2]), "=r"(r[3]) : "r"(addr));
}

__device__ __forceinline__ uint32_t smem_u32(const void* p) {
    uint32_t a;
    asm("{ .reg .u64 t; cvta.to.shared.u64 t, %1; cvt.u32.u64 %0, t; }" : "=r"(a) : "l"(p));
    return a;
}

__device__ __forceinline__ void cp16(uint32_t dst, const float* src) {
    asm volatile("cp.async.cg.shared.global [%0], [%1], 16;" :: "r"(dst), "l"(src));
}
#define CP_COMMIT() asm volatile("cp.async.commit_group;" ::: "memory")
__device__ __forceinline__ void cp_wait_n(int n) {
    if (n <= 0)      asm volatile("cp.async.wait_group 0;" ::: "memory");
    else if (n == 1) asm volatile("cp.async.wait_group 1;" ::: "memory");
    else             asm volatile("cp.async.wait_group 2;" ::: "memory");
}

// ------------------------- weight prep: round + fragment-pack -----------
// dst float index: ((d*(K/16)+kt)*N + n)*16 + tig*4 + e,  k = 16kt + tig + 4e
struct TSeg { const float* src; float* dst; int K; int N; int total; };
struct TArgs { TSeg seg[9]; };
__global__ void prep_weights(TArgs a) {
    int s = blockIdx.y;
    int i = blockIdx.x * 256 + threadIdx.x;
    TSeg sg = a.seg[s];
    if (i >= sg.total) return;
    int KN = sg.K * sg.N;
    int d = i / KN, r = i % KN;
    int k = r / sg.N, n = r % sg.N;
    int kt = k >> 4, kr = k & 15;
    int tig = kr & 3, e = kr >> 2;
    size_t dst = ((size_t)(d * (sg.K >> 4) + kt) * sg.N + n) * 16 + tig * 4 + e;
    sg.dst[dst] = roundtf(sg.src[i]);
}

// ------------------------- embedding gather (+ zero sums) ---------------
__global__ void embed_kernel(const int* __restrict__ id_idx,
                             const int* __restrict__ agn_idx,
                             const float* __restrict__ id_tab,
                             const float* __restrict__ agn_tab) {
    int t = blockIdx.x * blockDim.x + threadIdx.x;
    if (t < 3 * 2 * DNUM * 256) ((float*)g_sums3)[t] = 0.0f;
    if (t >= BSZ * 64) return;
    int b = t >> 6;
    int j = (t & 63) << 2;
    const int*   idx = id_idx;
    const float* tab = id_tab;
    int jj = j;
    if (j >= 128) { idx = agn_idx; tab = agn_tab; jj = j - 128; }
    int f = jj >> 4, e = jj & 15;
    int v = idx[b * NFEAT + f];
    float4 val = *(const float4*)(tab + ((size_t)f * VOCAB + v) * EDIM + e);
    val.x = roundtf(val.x); val.y = roundtf(val.y);
    val.z = roundtf(val.z); val.w = roundtf(val.w);
    *(float4*)(g_gate_in + (size_t)b * IND + j) = val;
}

// ------------------------- tensor-core GEMM ------------------------------
// C[d] = A[d] (BSZ x K, tf32-rounded) @ W(packed)[d] + bias[d]
// EPI: 0 = none + column stats, 1 = relu+round, 2 = 2*sigmoid
// BM=128, BK=16, 4-stage cp.async ring. 8 warps (4m x 2n). Warp tile 32 x (BN/2).
template <int BN, int EPI>
__global__ void __launch_bounds__(256, 2)
gemm_tc(const float* __restrict__ A, size_t aDomStride,
        const float* __restrict__ Wp,
        const float* __restrict__ bias,
        float* __restrict__ C,
        float* __restrict__ sums,
        int K, int N) {
    constexpr int BM = 128, BK = 16;
    constexpr int WN = BN / 2;               // 64 or 32
    constexpr int NI = WN / 8;               // 8 or 4
    constexpr int APAD = 20;
    constexpr int ABYTES = BM * APAD * 4;    // 10240
    constexpr int BBYTES = BN * 64;          // BN*16 floats
    constexpr int SB = ABYTES + BBYTES;      // bytes per stage
    constexpr int BQ = BN * 4;               // float4 quads per B chunk

    extern __shared__ __align__(16) float dynsm[];
    __shared__ float cs[BN], cq[BN];

    int d  = blockIdx.z;
    int bm = blockIdx.x * BM;
    int bn = blockIdx.y * BN;
    const float* Ad = A + (size_t)d * aDomStride + (size_t)bm * K;
    const float* Bd = Wp + (size_t)d * K * N + (size_t)bn * 16;
    float*       Cd = C + ((size_t)d * BSZ + bm) * N + bn;

    int tid  = threadIdx.x;
    int lane = tid & 31, wid = tid >> 5;
    int gid  = lane >> 2, tig = lane & 3;
    int wm   = wid >> 1,  wn  = wid & 1;

    int arow = tid >> 2, akc = (tid & 3) << 2;     // A: 64 rows x 16k, two row groups

    const float* Aptr0 = Ad + (size_t)arow * K + akc;
    const float* Aptr1 = Ad + (size_t)(arow + 64) * K + akc;

    uint32_t sbase = smem_u32(dynsm);

    // ldmatrix lane addressing: rows = warp m-base + (lane&15), col = (lane>>4)*4
    uint32_t lrow = lane & 15;
    uint32_t lcol = (lane >> 4) << 2;
    uint32_t aFragOff = ((wm * 32 + lrow) * APAD + lcol) << 2;

    float acc[2][NI][4] = {};

    auto stage = [&](int kt, int st) {
        uint32_t ab = sbase + st * SB;
        cp16(ab + ((arow * APAD + akc) << 2), Aptr0 + kt * 16);
        cp16(ab + (((arow + 64) * APAD + akc) << 2), Aptr1 + kt * 16);
        uint32_t bb = ab + ABYTES;
        const float* Bq = Bd + (size_t)kt * N * 16;
#pragma unroll
        for (int i = 0; i < BQ / 256; i++) {
            int q = tid + i * 256;
            cp16(bb + (q << 4), Bq + q * 4);
        }
        CP_COMMIT();
    };

    const int NCH = K / BK;                  // >= 4 always
    stage(0, 0); stage(1, 1); stage(2, 2);

    for (int c = 0; c < NCH; c++) {
        int st = c & 3;
        int pend = NCH - 1 - c; if (pend > 2) pend = 2;
        cp_wait_n(pend);
        __syncthreads();

        uint32_t aS = sbase + st * SB + aFragOff;
        const float* Bsf = dynsm + (st * SB + ABYTES) / 4;

        // B fragments: one LDS.128 per ni (covers both k-halves)
        float4 bq[NI];
#pragma unroll
        for (int ni = 0; ni < NI; ni++) {
            int cb = wn * WN + ni * 8 + gid;
            bq[ni] = *(const float4*)&Bsf[cb * 16 + tig * 4];
        }

        // A fragments: 2 x ldmatrix.x4 per k-half (mi = 0, 1)
#pragma unroll
        for (int ks = 0; ks < 2; ks++) {
            unsigned af[2][4];
            ldsm_x4(af[0], aS + ks * 32);
            ldsm_x4(af[1], aS + ks * 32 + 16 * APAD * 4);
#pragma unroll
            for (int mi = 0; mi < 2; mi++)
#pragma unroll
                for (int ni = 0; ni < NI; ni++) {
                    unsigned b2[2];
                    if (ks == 0) { b2[0] = __float_as_uint(bq[ni].x); b2[1] = __float_as_uint(bq[ni].y); }
                    else         { b2[0] = __float_as_uint(bq[ni].z); b2[1] = __float_as_uint(bq[ni].w); }
                    mma_tf32(acc[mi][ni], af[mi], b2);
                }
        }

        // prefetch tile c+3 into ring slot (c+3)&3 — safe: its previous
        // readers (iteration c-1) all passed this iteration's barrier.
        if (c + 3 < NCH) stage(c + 3, (c + 3) & 3);
    }

    if (EPI == 0) {
        if (tid < BN) { cs[tid] = 0.0f; cq[tid] = 0.0f; }
        __syncthreads();
    }

    float colS[NI][2] = {}, colQ[NI][2] = {};

#pragma unroll
    for (int mi = 0; mi < 2; mi++) {
        int r0 = wm * 32 + mi * 16 + gid;
#pragma unroll
        for (int ni = 0; ni < NI; ni++) {
            int col = wn * WN + ni * 8 + 2 * tig;
            float b0 = bias[d * N + bn + col];
            float b1 = bias[d * N + bn + col + 1];
            float v0 = acc[mi][ni][0] + b0;
            float v1 = acc[mi][ni][1] + b1;
            float v2 = acc[mi][ni][2] + b0;
            float v3 = acc[mi][ni][3] + b1;
            if (EPI == 1) {
                v0 = roundtf(fmaxf(v0, 0.0f)); v1 = roundtf(fmaxf(v1, 0.0f));
                v2 = roundtf(fmaxf(v2, 0.0f)); v3 = roundtf(fmaxf(v3, 0.0f));
            }
            if (EPI == 2) {
                v0 = 2.0f / (1.0f + expf(-v0)); v1 = 2.0f / (1.0f + expf(-v1));
                v2 = 2.0f / (1.0f + expf(-v2)); v3 = 2.0f / (1.0f + expf(-v3));
            }
            if (EPI == 0) {
                colS[ni][0] += v0 + v2;      colS[ni][1] += v1 + v3;
                colQ[ni][0] += v0 * v0 + v2 * v2;
                colQ[ni][1] += v1 * v1 + v3 * v3;
            }
            *(float2*)(Cd + (size_t)r0 * N + col)       = make_float2(v0, v1);
            *(float2*)(Cd + (size_t)(r0 + 8) * N + col) = make_float2(v2, v3);
        }
    }

    if (EPI == 0) {
#pragma unroll
        for (int ni = 0; ni < NI; ni++)
#pragma unroll
            for (int c2 = 0; c2 < 2; c2++) {
                float sv = colS[ni][c2], qv = colQ[ni][c2];
                sv += __shfl_xor_sync(0xffffffffu, sv, 16);
                sv += __shfl_xor_sync(0xffffffffu, sv, 8);
                sv += __shfl_xor_sync(0xffffffffu, sv, 4);
                qv += __shfl_xor_sync(0xffffffffu, qv, 16);
                qv += __shfl_xor_sync(0xffffffffu, qv, 8);
                qv += __shfl_xor_sync(0xffffffffu, qv, 4);
                if (gid == 0) {
                    int c = wn * WN + ni * 8 + 2 * tig + c2;
                    atomicAdd(&cs[c], sv);
                    atomicAdd(&cq[c], qv);
                }
            }
        __syncthreads();
        if (tid < BN) {
            atomicAdd(&sums[d * 256 + bn + tid], cs[tid]);
            atomicAdd(&sums[DNUM * 256 + d * 256 + bn + tid], cq[tid]);
        }
    }
}

// ------------------------- BN apply + gate ------------------------------
__global__ void bn_apply_gate(float* __restrict__ H, const float* __restrict__ G,
                              const float* __restrict__ sums,
                              const float* __restrict__ bng,
                              const float* __restrict__ bnb, int N) {
    size_t t = (size_t)blockIdx.x * blockDim.x + threadIdx.x;
    size_t total4 = (size_t)DNUM * BSZ * N / 4;
    if (t >= total4) return;
    size_t e = t * 4;
    int c = (int)(e % N);
    int d = (int)(e / ((size_t)BSZ * N));
    float4 h = *(float4*)(H + e);
    float4 g = *(const float4*)(G + e);
    float r[4] = {h.x, h.y, h.z, h.w};
    float gg[4] = {g.x, g.y, g.z, g.w};
#pragma unroll
    for (int j = 0; j < 4; j++) {
        int idx = d * 256 + c + j;
        float mean = sums[idx] * (1.0f / BSZ);
        float var  = sums[DNUM * 256 + idx] * (1.0f / BSZ) - mean * mean;
        float sc   = bng[d * N + c + j] * rsqrtf(var + 1e-5f);
        float sh   = bnb[d * N + c + j] - mean * sc;
        r[j] = roundtf(fmaxf(r[j] * sc + sh, 0.0f) * gg[j]);
    }
    *(float4*)(H + e) = make_float4(r[0], r[1], r[2], r[3]);
}

// ------------------------- final head -----------------------------------
__global__ void final_kernel(const float* __restrict__ H,
                             const int* __restrict__ dom,
                             const float* __restrict__ finW,
                             const float* __restrict__ finb,
                             float* __restrict__ out) {
    int warp = (blockIdx.x * blockDim.x + threadIdx.x) >> 5;
    int lane = threadIdx.x & 31;
    if (warp >= BSZ) return;
    int d = dom[warp];
    const float* h = H + ((size_t)d * BSZ + warp) * 64;
    const float* w = finW + d * 64;
    float s = h[lane] * w[lane] + h[lane + 32] * w[lane + 32];
#pragma unroll
    for (int o = 16; o > 0; o >>= 1) s += __shfl_down_sync(0xffffffffu, s, o);
    if (lane == 0) out[warp] = 1.0f / (1.0f + expf(-(s + finb[d])));
}

// ------------------------- dispatch helper ------------------------------
template <int EPI>
static void launch_gemm(const float* A, size_t aStride, const float* Wp,
                        const float* b, float* C, float* sums, int K, int N) {
    if (N >= 128) {
        constexpr int SM = 4 * (128 * 20 * 4 + 128 * 64);   // 73728
        cudaFuncSetAttribute(gemm_tc<128, EPI>, cudaFuncAttributeMaxDynamicSharedMemorySize, SM);
        dim3 grid(BSZ / 128, N / 128, DNUM);
        gemm_tc<128, EPI><<<grid, 256, SM>>>(A, aStride, Wp, b, C, sums, K, N);
    } else {
        constexpr int SM = 4 * (128 * 20 * 4 + 64 * 64);    // 57344
        cudaFuncSetAttribute(gemm_tc<64, EPI>, cudaFuncAttributeMaxDynamicSharedMemorySize, SM);
        dim3 grid(BSZ / 128, N / 64, DNUM);
        gemm_tc<64, EPI><<<grid, 256, SM>>>(A, aStride, Wp, b, C, sums, K, N);
    }
}

// ------------------------- launch --------------------------------------
extern "C" void kernel_launch(void* const* d_in, const int* in_sizes, int n_in,
                              void* d_out, int out_size) {
    const int*   id_idx    = (const int*)d_in[0];
    const int*   agn_idx   = (const int*)d_in[1];
    const int*   domain_id = (const int*)d_in[2];
    const float* id_tab    = (const float*)d_in[3];
    const float* agn_tab   = (const float*)d_in[4];
    const float* mlp_W[3]  = {(const float*)d_in[5],  (const float*)d_in[13], (const float*)d_in[21]};
    const float* mlp_b[3]  = {(const float*)d_in[6],  (const float*)d_in[14], (const float*)d_in[22]};
    const float* bn_g[3]   = {(const float*)d_in[7],  (const float*)d_in[15], (const float*)d_in[23]};
    const float* bn_b[3]   = {(const float*)d_in[8],  (const float*)d_in[16], (const float*)d_in[24]};
    const float* gW1[3]    = {(const float*)d_in[9],  (const float*)d_in[17], (const float*)d_in[25]};
    const float* gb1[3]    = {(const float*)d_in[10], (const float*)d_in[18], (const float*)d_in[26]};
    const float* gW2[3]    = {(const float*)d_in[11], (const float*)d_in[19], (const float*)d_in[27]};
    const float* gb2[3]    = {(const float*)d_in[12], (const float*)d_in[20], (const float*)d_in[28]};
    const float* finW      = (const float*)d_in[29];
    const float* finb      = (const float*)d_in[30];
    float*       out       = (float*)d_out;

    float *p_gate_in, *p_h0, *p_h1, *p_g1, *p_gt, *p_sums, *p_w;
    cudaGetSymbolAddress((void**)&p_gate_in, g_gate_in);
    cudaGetSymbolAddress((void**)&p_h0, g_h0);
    cudaGetSymbolAddress((void**)&p_h1, g_h1);
    cudaGetSymbolAddress((void**)&p_g1, g_g1);
    cudaGetSymbolAddress((void**)&p_gt, g_gt);
    cudaGetSymbolAddress((void**)&p_sums, g_sums3);
    cudaGetSymbolAddress((void**)&p_w, g_wrnd);

    const int dims[4] = {256, 256, 128, 64};

    // packed weights
    float* rW1[3]; float* rW2[3]; float* rWm[3];
    size_t off = 0;
    TArgs ta;
    int segi = 0, maxn = 0;
    for (int i = 0; i < 3; i++) {
        int N = dims[i + 1];
        rW1[i] = p_w + off;
        ta.seg[segi++] = {gW1[i], p_w + off, IND, N, DNUM * IND * N};           off += (size_t)DNUM * IND * N;
        rW2[i] = p_w + off;
        ta.seg[segi++] = {gW2[i], p_w + off, N, N, DNUM * N * N};               off += (size_t)DNUM * N * N;
        rWm[i] = p_w + off;
        ta.seg[segi++] = {mlp_W[i], p_w + off, dims[i], N, DNUM * dims[i] * N}; off += (size_t)DNUM * dims[i] * N;
    }
    for (int s = 0; s < 9; s++) if (ta.seg[s].total > maxn) maxn = ta.seg[s].total;

    dim3 rg((maxn + 255) / 256, 9);
    prep_weights<<<rg, 256>>>(ta);

    embed_kernel<<<(BSZ * 64 + 255) / 256, 256>>>(id_idx, agn_idx, id_tab, agn_tab);

    float* hbuf[2] = {p_h0, p_h1};
    const float* hprev = nullptr;

    for (int i = 0; i < 3; i++) {
        int Kmlp = dims[i];
        int N    = dims[i + 1];
        float* hout = hbuf[i & 1];
        float* sums = p_sums + (size_t)i * 2 * DNUM * 256;

        launch_gemm<1>(p_gate_in, 0, rW1[i], gb1[i], p_g1, nullptr, IND, N);
        launch_gemm<2>(p_g1, (size_t)BSZ * N, rW2[i], gb2[i], p_gt, nullptr, N, N);
        if (i == 0)
            launch_gemm<0>(p_gate_in, 0, rWm[i], mlp_b[i], hout, sums, IND, N);
        else
            launch_gemm<0>(hprev, (size_t)BSZ * Kmlp, rWm[i], mlp_b[i], hout, sums, Kmlp, N);

        size_t tot4 = (size_t)DNUM * BSZ * N / 4;
        bn_apply_gate<<<(unsigned)((tot4 + 255) / 256), 256>>>(hout, p_gt, sums, bn_g[i], bn_b[i], N);

        hprev = hout;
    }

    final_kernel<<<BSZ / 8, 256>>>(hprev, domain_id, finW, finb, out);
}

// round 10
// speedup vs baseline: 1.7418x; 1.0722x over previous
#include <cuda_runtime.h>
#include <math.h>
#include <stdint.h>

#define BSZ   32768
#define IND   256
#define NFEAT 8
#define EDIM  16
#define VOCAB 100000
#define DNUM  4

// ------------------------- scratch (device globals; no allocs) ----------
__device__ float g_gate_in[(size_t)BSZ * IND];
__device__ float g_h0[(size_t)DNUM * BSZ * 256];
__device__ float g_h1[(size_t)DNUM * BSZ * 256];
__device__ float g_g1[(size_t)DNUM * BSZ * 256];
__device__ float g_sums3[3][2 * DNUM * 256];
__device__ float g_wrnd[1300000];                 // packed tf32 weights

// ------------------------- helpers --------------------------------------
__device__ __forceinline__ unsigned f2tf32(float x) {
    unsigned r;
    asm("cvt.rna.tf32.f32 %0, %1;" : "=r"(r) : "f"(x));
    return r;
}
__device__ __forceinline__ float roundtf(float x) { return __uint_as_float(f2tf32(x)); }

__device__ __forceinline__ void mma_tf32(float c[4], const unsigned a[4], const unsigned b[2]) {
    asm volatile(
        "mma.sync.aligned.m16n8k8.row.col.f32.tf32.tf32.f32 "
        "{%0,%1,%2,%3}, {%4,%5,%6,%7}, {%8,%9}, {%0,%1,%2,%3};"
        : "+f"(c[0]), "+f"(c[1]), "+f"(c[2]), "+f"(c[3])
        : "r"(a[0]), "r"(a[1]), "r"(a[2]), "r"(a[3]), "r"(b[0]), "r"(b[1]));
}

__device__ __forceinline__ void ldsm_x4(unsigned r[4], uint32_t addr) {
    asm volatile("ldmatrix.sync.aligned.m8n8.x4.shared.b16 {%0,%1,%2,%3}, [%4];"
                 : "=r"(r[0]), "=r"(r[1]), "=r"(r[2]), "=r"(r[3]) : "r"(addr));
}

__device__ __forceinline__ uint32_t smem_u32(const void* p) {
    uint32_t a;
    asm("{ .reg .u64 t; cvta.to.shared.u64 t, %1; cvt.u32.u64 %0, t; }" : "=r"(a) : "l"(p));
    return a;
}

__device__ __forceinline__ void cp16(uint32_t dst, const float* src) {
    asm volatile("cp.async.cg.shared.global [%0], [%1], 16;" :: "r"(dst), "l"(src));
}
#define CP_COMMIT() asm volatile("cp.async.commit_group;" ::: "memory")
__device__ __forceinline__ void cp_wait_n(int n) {
    if (n <= 0)      asm volatile("cp.async.wait_group 0;" ::: "memory");
    else if (n == 1) asm volatile("cp.async.wait_group 1;" ::: "memory");
    else if (n == 2) asm volatile("cp.async.wait_group 2;" ::: "memory");
    else             asm volatile("cp.async.wait_group 3;" ::: "memory");
}

// ------------------------- weight prep: round + fragment-pack -----------
// dst float index: ((d*(K/16)+kt)*N + n)*16 + tig*4 + e,  k = 16kt + tig + 4e
struct TSeg { const float* src; float* dst; int K; int N; int total; };
struct TArgs { TSeg seg[9]; };
__global__ void prep_weights(TArgs a) {
    int s = blockIdx.y;
    int i = blockIdx.x * 256 + threadIdx.x;
    TSeg sg = a.seg[s];
    if (i >= sg.total) return;
    int KN = sg.K * sg.N;
    int d = i / KN, r = i % KN;
    int k = r / sg.N, n = r % sg.N;
    int kt = k >> 4, kr = k & 15;
    int tig = kr & 3, e = kr >> 2;
    size_t dst = ((size_t)(d * (sg.K >> 4) + kt) * sg.N + n) * 16 + tig * 4 + e;
    sg.dst[dst] = roundtf(sg.src[i]);
}

// ------------------------- embedding gather (+ zero sums) ---------------
__global__ void embed_kernel(const int* __restrict__ id_idx,
                             const int* __restrict__ agn_idx,
                             const float* __restrict__ id_tab,
                             const float* __restrict__ agn_tab) {
    int t = blockIdx.x * blockDim.x + threadIdx.x;
    if (t < 3 * 2 * DNUM * 256) ((float*)g_sums3)[t] = 0.0f;
    if (t >= BSZ * 64) return;
    int b = t >> 6;
    int j = (t & 63) << 2;
    const int*   idx = id_idx;
    const float* tab = id_tab;
    int jj = j;
    if (j >= 128) { idx = agn_idx; tab = agn_tab; jj = j - 128; }
    int f = jj >> 4, e = jj & 15;
    int v = idx[b * NFEAT + f];
    float4 val = *(const float4*)(tab + ((size_t)f * VOCAB + v) * EDIM + e);
    val.x = roundtf(val.x); val.y = roundtf(val.y);
    val.z = roundtf(val.z); val.w = roundtf(val.w);
    *(float4*)(g_gate_in + (size_t)b * IND + j) = val;
}

// ------------------------- tensor-core GEMM ------------------------------
// C[d] = A[d] (BSZ x K, tf32-rounded) @ W(packed)[d] + bias[d]
// EPI: 0 = none + column stats (mlp pre-BN)
//      1 = relu + tf32 round (g1)
//      3 = gate = 2*sigmoid(acc+bias); C := round(relu(C*sc + sh) * gate)
//          (fused BN-apply + gate; sc/sh from sums+bng+bnb, in-place on C)
// BM=128, BK=16, 5-stage cp.async ring. 8 warps (4m x 2n). Warp tile 32 x (BN/2).
template <int BN, int EPI>
__global__ void __launch_bounds__(256, 2)
gemm_tc(const float* __restrict__ A, size_t aDomStride,
        const float* __restrict__ Wp,
        const float* __restrict__ bias,
        float* __restrict__ C,
        float* __restrict__ sums,
        const float* __restrict__ bng,
        const float* __restrict__ bnb,
        int K, int N) {
    constexpr int BM = 128, BK = 16;
    constexpr int WN = BN / 2;               // 64 or 32
    constexpr int NI = WN / 8;               // 8 or 4
    constexpr int APAD = 20;
    constexpr int ABYTES = BM * APAD * 4;    // 10240
    constexpr int BBYTES = BN * 64;          // BN*16 floats
    constexpr int SB = ABYTES + BBYTES;      // bytes per stage
    constexpr int BQ = BN * 4;               // float4 quads per B chunk
    constexpr int NS = 5;                    // pipeline stages

    extern __shared__ __align__(16) float dynsm[];
    __shared__ float cs[BN], cq[BN];

    int d  = blockIdx.z;
    int bm = blockIdx.x * BM;
    int bn = blockIdx.y * BN;
    const float* Ad = A + (size_t)d * aDomStride + (size_t)bm * K;
    const float* Bd = Wp + (size_t)d * K * N + (size_t)bn * 16;
    float*       Cd = C + ((size_t)d * BSZ + bm) * N + bn;

    int tid  = threadIdx.x;
    int lane = tid & 31, wid = tid >> 5;
    int gid  = lane >> 2, tig = lane & 3;
    int wm   = wid >> 1,  wn  = wid & 1;

    int arow = tid >> 2, akc = (tid & 3) << 2;     // A: 64 rows x 16k, two row groups

    const float* Aptr0 = Ad + (size_t)arow * K + akc;
    const float* Aptr1 = Ad + (size_t)(arow + 64) * K + akc;

    uint32_t sbase = smem_u32(dynsm);

    // ldmatrix lane addressing: rows = warp m-base + (lane&15), col = (lane>>4)*4
    uint32_t lrow = lane & 15;
    uint32_t lcol = (lane >> 4) << 2;
    uint32_t aFragOff = ((wm * 32 + lrow) * APAD + lcol) << 2;

    float acc[2][NI][4] = {};

    auto stage = [&](int kt, int st) {
        uint32_t ab = sbase + st * SB;
        cp16(ab + ((arow * APAD + akc) << 2), Aptr0 + kt * 16);
        cp16(ab + (((arow + 64) * APAD + akc) << 2), Aptr1 + kt * 16);
        uint32_t bb = ab + ABYTES;
        const float* Bq = Bd + (size_t)kt * N * 16;
#pragma unroll
        for (int i = 0; i < BQ / 256; i++) {
            int q = tid + i * 256;
            cp16(bb + (q << 4), Bq + q * 4);
        }
        CP_COMMIT();
    };

    const int NCH = K / BK;                  // >= 4 always
    const int npro = NCH < (NS - 1) ? NCH : (NS - 1);
    for (int t = 0; t < npro; t++) stage(t, t);

    int st = 0, sslot = npro;                // npro <= 4 < NS
    for (int c = 0; c < NCH; c++) {
        int pend = NCH - 1 - c; if (pend > NS - 2) pend = NS - 2;
        cp_wait_n(pend);
        __syncthreads();

        uint32_t aS = sbase + st * SB + aFragOff;
        const float* Bsf = dynsm + (st * SB + ABYTES) / 4;

        // B fragments: one LDS.128 per ni (covers both k-halves)
        float4 bq[NI];
#pragma unroll
        for (int ni = 0; ni < NI; ni++) {
            int cb = wn * WN + ni * 8 + gid;
            bq[ni] = *(const float4*)&Bsf[cb * 16 + tig * 4];
        }

        // A fragments: 2 x ldmatrix.x4 per k-half (mi = 0, 1)
#pragma unroll
        for (int ks = 0; ks < 2; ks++) {
            unsigned af[2][4];
            ldsm_x4(af[0], aS + ks * 32);
            ldsm_x4(af[1], aS + ks * 32 + 16 * APAD * 4);
#pragma unroll
            for (int mi = 0; mi < 2; mi++)
#pragma unroll
                for (int ni = 0; ni < NI; ni++) {
                    unsigned b2[2];
                    if (ks == 0) { b2[0] = __float_as_uint(bq[ni].x); b2[1] = __float_as_uint(bq[ni].y); }
                    else         { b2[0] = __float_as_uint(bq[ni].z); b2[1] = __float_as_uint(bq[ni].w); }
                    mma_tf32(acc[mi][ni], af[mi], b2);
                }
        }

        if (c + NS - 1 < NCH) {
            stage(c + NS - 1, sslot);
            if (++sslot == NS) sslot = 0;
        }
        if (++st == NS) st = 0;
    }

    if (EPI == 0) {
        if (tid < BN) { cs[tid] = 0.0f; cq[tid] = 0.0f; }
        __syncthreads();
    }
    if (EPI == 3) {
        // per-column BN scale/shift from this layer's sums
        if (tid < BN) {
            int idxc = d * 256 + bn + tid;
            float mean = sums[idxc] * (1.0f / BSZ);
            float var  = sums[DNUM * 256 + idxc] * (1.0f / BSZ) - mean * mean;
            float sc   = bng[d * N + bn + tid] * rsqrtf(var + 1e-5f);
            cs[tid] = sc;
            cq[tid] = bnb[d * N + bn + tid] - mean * sc;
        }
        __syncthreads();
    }

    float colS[NI][2] = {}, colQ[NI][2] = {};

#pragma unroll
    for (int mi = 0; mi < 2; mi++) {
        int r0 = wm * 32 + mi * 16 + gid;
#pragma unroll
        for (int ni = 0; ni < NI; ni++) {
            int col = wn * WN + ni * 8 + 2 * tig;
            float b0 = bias[d * N + bn + col];
            float b1 = bias[d * N + bn + col + 1];
            float v0 = acc[mi][ni][0] + b0;
            float v1 = acc[mi][ni][1] + b1;
            float v2 = acc[mi][ni][2] + b0;
            float v3 = acc[mi][ni][3] + b1;
            float* p0 = Cd + (size_t)r0 * N + col;
            float* p1 = Cd + (size_t)(r0 + 8) * N + col;
            if (EPI == 1) {
                v0 = roundtf(fmaxf(v0, 0.0f)); v1 = roundtf(fmaxf(v1, 0.0f));
                v2 = roundtf(fmaxf(v2, 0.0f)); v3 = roundtf(fmaxf(v3, 0.0f));
            }
            if (EPI == 3) {
                // v* are gates; read h_pre in place, apply BN + relu + gate
                float g0 = 2.0f / (1.0f + expf(-v0));
                float g1 = 2.0f / (1.0f + expf(-v1));
                float g2 = 2.0f / (1.0f + expf(-v2));
                float g3 = 2.0f / (1.0f + expf(-v3));
                float2 h01 = *(float2*)p0;
                float2 h23 = *(float2*)p1;
                float sc0 = cs[col], sh0 = cq[col];
                float sc1 = cs[col + 1], sh1 = cq[col + 1];
                v0 = roundtf(fmaxf(h01.x * sc0 + sh0, 0.0f) * g0);
                v1 = roundtf(fmaxf(h01.y * sc1 + sh1, 0.0f) * g1);
                v2 = roundtf(fmaxf(h23.x * sc0 + sh0, 0.0f) * g2);
                v3 = roundtf(fmaxf(h23.y * sc1 + sh1, 0.0f) * g3);
            }
            if (EPI == 0) {
                colS[ni][0] += v0 + v2;      colS[ni][1] += v1 + v3;
                colQ[ni][0] += v0 * v0 + v2 * v2;
                colQ[ni][1] += v1 * v1 + v3 * v3;
            }
            *(float2*)p0 = make_float2(v0, v1);
            *(float2*)p1 = make_float2(v2, v3);
        }
    }

    if (EPI == 0) {
#pragma unroll
        for (int ni = 0; ni < NI; ni++)
#pragma unroll
            for (int c2 = 0; c2 < 2; c2++) {
                float sv = colS[ni][c2], qv = colQ[ni][c2];
                sv += __shfl_xor_sync(0xffffffffu, sv, 16);
                sv += __shfl_xor_sync(0xffffffffu, sv, 8);
                sv += __shfl_xor_sync(0xffffffffu, sv, 4);
                qv += __shfl_xor_sync(0xffffffffu, qv, 16);
                qv += __shfl_xor_sync(0xffffffffu, qv, 8);
                qv += __shfl_xor_sync(0xffffffffu, qv, 4);
                if (gid == 0) {
                    int c = wn * WN + ni * 8 + 2 * tig + c2;
                    atomicAdd(&cs[c], sv);
                    atomicAdd(&cq[c], qv);
                }
            }
        __syncthreads();
        if (tid < BN) {
            atomicAdd(&sums[d * 256 + bn + tid], cs[tid]);
            atomicAdd(&sums[DNUM * 256 + d * 256 + bn + tid], cq[tid]);
        }
    }
}

// ------------------------- final head -----------------------------------
__global__ void final_kernel(const float* __restrict__ H,
                             const int* __restrict__ dom,
                             const float* __restrict__ finW,
                             const float* __restrict__ finb,
                             float* __restrict__ out) {
    int warp = (blockIdx.x * blockDim.x + threadIdx.x) >> 5;
    int lane = threadIdx.x & 31;
    if (warp >= BSZ) return;
    int d = dom[warp];
    const float* h = H + ((size_t)d * BSZ + warp) * 64;
    const float* w = finW + d * 64;
    float s = h[lane] * w[lane] + h[lane + 32] * w[lane + 32];
#pragma unroll
    for (int o = 16; o > 0; o >>= 1) s += __shfl_down_sync(0xffffffffu, s, o);
    if (lane == 0) out[warp] = 1.0f / (1.0f + expf(-(s + finb[d])));
}

// ------------------------- dispatch helper ------------------------------
template <int EPI>
static void launch_gemm(const float* A, size_t aStride, const float* Wp,
                        const float* b, float* C, float* sums,
                        const float* bng, const float* bnb, int K, int N) {
    if (N >= 128) {
        constexpr int SM = 5 * (128 * 20 * 4 + 128 * 64);   // 92160
        cudaFuncSetAttribute(gemm_tc<128, EPI>, cudaFuncAttributeMaxDynamicSharedMemorySize, SM);
        dim3 grid(BSZ / 128, N / 128, DNUM);
        gemm_tc<128, EPI><<<grid, 256, SM>>>(A, aStride, Wp, b, C, sums, bng, bnb, K, N);
    } else {
        constexpr int SM = 5 * (128 * 20 * 4 + 64 * 64);    // 71680
        cudaFuncSetAttribute(gemm_tc<64, EPI>, cudaFuncAttributeMaxDynamicSharedMemorySize, SM);
        dim3 grid(BSZ / 128, N / 64, DNUM);
        gemm_tc<64, EPI><<<grid, 256, SM>>>(A, aStride, Wp, b, C, sums, bng, bnb, K, N);
    }
}

// ------------------------- launch --------------------------------------
extern "C" void kernel_launch(void* const* d_in, const int* in_sizes, int n_in,
                              void* d_out, int out_size) {
    const int*   id_idx    = (const int*)d_in[0];
    const int*   agn_idx   = (const int*)d_in[1];
    const int*   domain_id = (const int*)d_in[2];
    const float* id_tab    = (const float*)d_in[3];
    const float* agn_tab   = (const float*)d_in[4];
    const float* mlp_W[3]  = {(const float*)d_in[5],  (const float*)d_in[13], (const float*)d_in[21]};
    const float* mlp_b[3]  = {(const float*)d_in[6],  (const float*)d_in[14], (const float*)d_in[22]};
    const float* bn_g[3]   = {(const float*)d_in[7],  (const float*)d_in[15], (const float*)d_in[23]};
    const float* bn_b[3]   = {(const float*)d_in[8],  (const float*)d_in[16], (const float*)d_in[24]};
    const float* gW1[3]    = {(const float*)d_in[9],  (const float*)d_in[17], (const float*)d_in[25]};
    const float* gb1[3]    = {(const float*)d_in[10], (const float*)d_in[18], (const float*)d_in[26]};
    const float* gW2[3]    = {(const float*)d_in[11], (const float*)d_in[19], (const float*)d_in[27]};
    const float* gb2[3]    = {(const float*)d_in[12], (const float*)d_in[20], (const float*)d_in[28]};
    const float* finW      = (const float*)d_in[29];
    const float* finb      = (const float*)d_in[30];
    float*       out       = (float*)d_out;

    float *p_gate_in, *p_h0, *p_h1, *p_g1, *p_sums, *p_w;
    cudaGetSymbolAddress((void**)&p_gate_in, g_gate_in);
    cudaGetSymbolAddress((void**)&p_h0, g_h0);
    cudaGetSymbolAddress((void**)&p_h1, g_h1);
    cudaGetSymbolAddress((void**)&p_g1, g_g1);
    cudaGetSymbolAddress((void**)&p_sums, g_sums3);
    cudaGetSymbolAddress((void**)&p_w, g_wrnd);

    const int dims[4] = {256, 256, 128, 64};

    // packed weights
    float* rW1[3]; float* rW2[3]; float* rWm[3];
    size_t off = 0;
    TArgs ta;
    int segi = 0, maxn = 0;
    for (int i = 0; i < 3; i++) {
        int N = dims[i + 1];
        rW1[i] = p_w + off;
        ta.seg[segi++] = {gW1[i], p_w + off, IND, N, DNUM * IND * N};           off += (size_t)DNUM * IND * N;
        rW2[i] = p_w + off;
        ta.seg[segi++] = {gW2[i], p_w + off, N, N, DNUM * N * N};               off += (size_t)DNUM * N * N;
        rWm[i] = p_w + off;
        ta.seg[segi++] = {mlp_W[i], p_w + off, dims[i], N, DNUM * dims[i] * N}; off += (size_t)DNUM * dims[i] * N;
    }
    for (int s = 0; s < 9; s++) if (ta.seg[s].total > maxn) maxn = ta.seg[s].total;

    dim3 rg((maxn + 255) / 256, 9);
    prep_weights<<<rg, 256>>>(ta);

    embed_kernel<<<(BSZ * 64 + 255) / 256, 256>>>(id_idx, agn_idx, id_tab, agn_tab);

    float* hbuf[2] = {p_h0, p_h1};
    const float* hprev = nullptr;

    for (int i = 0; i < 3; i++) {
        int Kmlp = dims[i];
        int N    = dims[i + 1];
        float* hout = hbuf[i & 1];
        float* sums = p_sums + (size_t)i * 2 * DNUM * 256;

        // 1) h_pre = X @ mlp_W + mlp_b  (+ column stats)
        if (i == 0)
            launch_gemm<0>(p_gate_in, 0, rWm[i], mlp_b[i], hout, sums, nullptr, nullptr, IND, N);
        else
            launch_gemm<0>(hprev, (size_t)BSZ * Kmlp, rWm[i], mlp_b[i], hout, sums, nullptr, nullptr, Kmlp, N);

        // 2) g1 = relu(gate_in @ gW1 + gb1)
        launch_gemm<1>(p_gate_in, 0, rW1[i], gb1[i], p_g1, nullptr, nullptr, nullptr, IND, N);

        // 3) gate = 2*sigmoid(g1 @ gW2 + gb2); h = round(relu(bn(h_pre)) * gate)  [in place]
        launch_gemm<3>(p_g1, (size_t)BSZ * N, rW2[i], gb2[i], hout, sums, bn_g[i], bn_b[i], N, N);

        hprev = hout;
    }

    final_kernel<<<BSZ / 8, 256>>>(hprev, domain_id, finW, finb, out);
}

// round 11
// speedup vs baseline: 2.3782x; 1.3654x over previous
#include <cuda_runtime.h>
#include <cuda_fp16.h>
#include <math.h>
#include <stdint.h>

#define BSZ   32768
#define IND   256
#define NFEAT 8
#define EDIM  16
#define VOCAB 100000
#define DNUM  4

// ------------------------- scratch (device globals; no allocs) ----------
__device__ __align__(16) __half g_gate_h[(size_t)BSZ * IND];          // fp16 gate_in
__device__ __align__(16) __half g_g1h[(size_t)DNUM * BSZ * 256];      // fp16 g1
__device__ __align__(16) __half g_hh[(size_t)DNUM * BSZ * 256];       // fp16 h
__device__ float g_hpre[(size_t)DNUM * BSZ * 256];                    // fp32 h_pre
__device__ float g_sums3[3][2 * DNUM * 256];
__device__ __align__(16) __half g_wh[1300000];                        // packed fp16 weights

// ------------------------- helpers --------------------------------------
__device__ __forceinline__ void mma_f16(float c[4], const unsigned a[4], const unsigned b[2]) {
    asm volatile(
        "mma.sync.aligned.m16n8k16.row.col.f32.f16.f16.f32 "
        "{%0,%1,%2,%3}, {%4,%5,%6,%7}, {%8,%9}, {%0,%1,%2,%3};"
        : "+f"(c[0]), "+f"(c[1]), "+f"(c[2]), "+f"(c[3])
        : "r"(a[0]), "r"(a[1]), "r"(a[2]), "r"(a[3]), "r"(b[0]), "r"(b[1]));
}

__device__ __forceinline__ void ldsm_x4(unsigned r[4], uint32_t addr) {
    asm volatile("ldmatrix.sync.aligned.m8n8.x4.shared.b16 {%0,%1,%2,%3}, [%4];"
                 : "=r"(r[0]), "=r"(r[1]), "=r"(r[2]), "=r"(r[3]) : "r"(addr));
}

__device__ __forceinline__ uint32_t smem_u32(const void* p) {
    uint32_t a;
    asm("{ .reg .u64 t; cvta.to.shared.u64 t, %1; cvt.u32.u64 %0, t; }" : "=r"(a) : "l"(p));
    return a;
}

__device__ __forceinline__ void cp16(uint32_t dst, const void* src) {
    asm volatile("cp.async.cg.shared.global [%0], [%1], 16;" :: "r"(dst), "l"(src));
}
#define CP_COMMIT() asm volatile("cp.async.commit_group;" ::: "memory")
__device__ __forceinline__ void cp_wait_n(int n) {
    if (n <= 0)      asm volatile("cp.async.wait_group 0;" ::: "memory");
    else if (n == 1) asm volatile("cp.async.wait_group 1;" ::: "memory");
    else if (n == 2) asm volatile("cp.async.wait_group 2;" ::: "memory");
    else             asm volatile("cp.async.wait_group 3;" ::: "memory");
}

// ------------------------- weight prep: fp16 + fragment-pack ------------
// For k-tile kt (16 k), column n: 16 halves, grouped per tig:
//   group tig holds k = {2tig, 2tig+1, 2tig+8, 2tig+9}
// dst half index: ((d*(K/16)+kt)*N + n)*16 + tig*4 + pos
struct TSeg { const float* src; __half* dst; int K; int N; int total; };
struct TArgs { TSeg seg[9]; };
__global__ void prep_weights(TArgs a) {
    int s = blockIdx.y;
    int i = blockIdx.x * 256 + threadIdx.x;
    TSeg sg = a.seg[s];
    if (i >= sg.total) return;
    int KN = sg.K * sg.N;
    int d = i / KN, r = i % KN;
    int k = r / sg.N, n = r % sg.N;
    int kt = k >> 4, kr = k & 15;
    int tig = (kr & 7) >> 1;
    int pos = (kr & 1) | ((kr >> 3) << 1);
    size_t dst = ((size_t)(d * (sg.K >> 4) + kt) * sg.N + n) * 16 + tig * 4 + pos;
    sg.dst[dst] = __float2half_rn(sg.src[i]);
}

// ------------------------- embedding gather (+ zero sums) ---------------
__global__ void embed_kernel(const int* __restrict__ id_idx,
                             const int* __restrict__ agn_idx,
                             const float* __restrict__ id_tab,
                             const float* __restrict__ agn_tab) {
    int t = blockIdx.x * blockDim.x + threadIdx.x;
    if (t < 3 * 2 * DNUM * 256) ((float*)g_sums3)[t] = 0.0f;
    if (t >= BSZ * 64) return;
    int b = t >> 6;
    int j = (t & 63) << 2;
    const int*   idx = id_idx;
    const float* tab = id_tab;
    int jj = j;
    if (j >= 128) { idx = agn_idx; tab = agn_tab; jj = j - 128; }
    int f = jj >> 4, e = jj & 15;
    int v = idx[b * NFEAT + f];
    float4 val = *(const float4*)(tab + ((size_t)f * VOCAB + v) * EDIM + e);
    __half* p = g_gate_h + (size_t)b * IND + j;
    *(__half2*)(p)     = __floats2half2_rn(val.x, val.y);
    *(__half2*)(p + 2) = __floats2half2_rn(val.z, val.w);
}

// ------------------------- fp16 tensor-core GEMM -------------------------
// acc[d] = A[d] (BSZ x K, fp16) @ W(packed fp16)[d] + bias[d]   (fp32 accum)
// EPI 0: Cf := acc (fp32 h_pre) + column stats into sums
// EPI 1: Ch := half(relu(acc))
// EPI 3: gate = 2*sigmoid(acc); Ch := half(relu(Cf*sc + sh) * gate)
// BM=128, BK=16 (one m16n8k16 per frag pair), 5-stage cp.async ring.
// 8 warps (4m x 2n), warp tile 32 x (BN/2).
template <int BN, int EPI>
__global__ void __launch_bounds__(256, 2)
gemm_tc(const __half* __restrict__ A, size_t aDomStride,
        const __half* __restrict__ Wp,
        const float* __restrict__ bias,
        float* __restrict__ Cf,
        __half* __restrict__ Ch,
        float* __restrict__ sums,
        const float* __restrict__ bng,
        const float* __restrict__ bnb,
        int K, int N) {
    constexpr int BM = 128, BK = 16;
    constexpr int WN = BN / 2;               // 64 or 32
    constexpr int NI = WN / 8;               // 8 or 4
    constexpr int ASTRIDE = 48;              // bytes per A row (32 + 16 pad)
    constexpr int ABYTES = BM * ASTRIDE;     // 6144
    constexpr int BBYTES = BN * 32;          // 16 halves per col
    constexpr int SB = ABYTES + BBYTES;
    constexpr int NS = 5;

    extern __shared__ __align__(16) char dynsm[];
    __shared__ float cs[BN], cq[BN];

    int d  = blockIdx.z;
    int bm = blockIdx.x * BM;
    int bn = blockIdx.y * BN;
    const __half* Ad = A + (size_t)d * aDomStride + (size_t)bm * K;
    const __half* Bd = Wp + (size_t)d * K * N + (size_t)bn * 16;
    float*  Cfd = Cf ? Cf + ((size_t)d * BSZ + bm) * N + bn : nullptr;
    __half* Chd = Ch ? Ch + ((size_t)d * BSZ + bm) * N + bn : nullptr;

    int tid  = threadIdx.x;
    int lane = tid & 31, wid = tid >> 5;
    int gid  = lane >> 2, tig = lane & 3;
    int wm   = wid >> 1,  wn  = wid & 1;

    // A staging: 128 rows x 32 bytes; 2 threads per row (16B each)
    int arow = tid >> 1;
    int ahalf = (tid & 1);                   // 0 or 1 (x8 halves / x16 bytes)
    const __half* Aptr = Ad + (size_t)arow * K + ahalf * 8;

    uint32_t sbase = smem_u32(dynsm);

    // ldmatrix lane addressing: row = wm*32 + mi*16 + (lane&15), kcol-16B = lane>>4
    uint32_t lrow = lane & 15;
    uint32_t aFragOff = (wm * 32 + lrow) * ASTRIDE + (lane >> 4) * 16;

    float acc[2][NI][4] = {};

    auto stage = [&](int kt, int st) {
        uint32_t ab = sbase + st * SB;
        cp16(ab + arow * ASTRIDE + ahalf * 16, Aptr + kt * 16);
        uint32_t bb = ab + ABYTES;
        const __half* Bq = Bd + (size_t)kt * N * 16;
        if (BN == 128) {
            cp16(bb + tid * 16, Bq + tid * 8);
        } else {
            if (tid < 128) cp16(bb + tid * 16, Bq + tid * 8);
        }
        CP_COMMIT();
    };

    const int NCH = K / BK;                  // >= 4 always
    const int npro = NCH < (NS - 1) ? NCH : (NS - 1);
    for (int t = 0; t < npro; t++) stage(t, t);

    int st = 0, sslot = npro;
    for (int c = 0; c < NCH; c++) {
        int pend = NCH - 1 - c; if (pend > NS - 2) pend = NS - 2;
        cp_wait_n(pend);
        __syncthreads();

        uint32_t aS = sbase + st * SB + aFragOff;
        const char* Bbase = dynsm + st * SB + ABYTES;

        // B fragments: one LDS.64 per ni (4 halves: k 2tig,2tig+1,2tig+8,2tig+9)
        uint2 bq[NI];
#pragma unroll
        for (int ni = 0; ni < NI; ni++) {
            int cb = wn * WN + ni * 8 + gid;
            bq[ni] = *(const uint2*)(Bbase + cb * 32 + tig * 8);
        }

        // A fragments: one ldmatrix.x4 per mi (covers full k=16)
        unsigned af[2][4];
        ldsm_x4(af[0], aS);
        ldsm_x4(af[1], aS + 16 * ASTRIDE);

#pragma unroll
        for (int mi = 0; mi < 2; mi++)
#pragma unroll
            for (int ni = 0; ni < NI; ni++)
                mma_f16(acc[mi][ni], af[mi], (const unsigned*)&bq[ni]);

        if (c + NS - 1 < NCH) {
            stage(c + NS - 1, sslot);
            if (++sslot == NS) sslot = 0;
        }
        if (++st == NS) st = 0;
    }

    if (EPI == 0) {
        if (tid < BN) { cs[tid] = 0.0f; cq[tid] = 0.0f; }
        __syncthreads();
    }
    if (EPI == 3) {
        if (tid < BN) {
            int idxc = d * 256 + bn + tid;
            float mean = sums[idxc] * (1.0f / BSZ);
            float var  = sums[DNUM * 256 + idxc] * (1.0f / BSZ) - mean * mean;
            float sc   = bng[d * N + bn + tid] * rsqrtf(var + 1e-5f);
            cs[tid] = sc;
            cq[tid] = bnb[d * N + bn + tid] - mean * sc;
        }
        __syncthreads();
    }

    float colS[NI][2] = {}, colQ[NI][2] = {};

#pragma unroll
    for (int mi = 0; mi < 2; mi++) {
        int r0 = wm * 32 + mi * 16 + gid;
#pragma unroll
        for (int ni = 0; ni < NI; ni++) {
            int col = wn * WN + ni * 8 + 2 * tig;
            float b0 = bias[d * N + bn + col];
            float b1 = bias[d * N + bn + col + 1];
            float v0 = acc[mi][ni][0] + b0;
            float v1 = acc[mi][ni][1] + b1;
            float v2 = acc[mi][ni][2] + b0;
            float v3 = acc[mi][ni][3] + b1;
            if (EPI == 0) {
                colS[ni][0] += v0 + v2;      colS[ni][1] += v1 + v3;
                colQ[ni][0] += v0 * v0 + v2 * v2;
                colQ[ni][1] += v1 * v1 + v3 * v3;
                *(float2*)(Cfd + (size_t)r0 * N + col)       = make_float2(v0, v1);
                *(float2*)(Cfd + (size_t)(r0 + 8) * N + col) = make_float2(v2, v3);
            }
            if (EPI == 1) {
                *(__half2*)(Chd + (size_t)r0 * N + col) =
                    __floats2half2_rn(fmaxf(v0, 0.0f), fmaxf(v1, 0.0f));
                *(__half2*)(Chd + (size_t)(r0 + 8) * N + col) =
                    __floats2half2_rn(fmaxf(v2, 0.0f), fmaxf(v3, 0.0f));
            }
            if (EPI == 3) {
                float g0 = 2.0f / (1.0f + expf(-v0));
                float g1 = 2.0f / (1.0f + expf(-v1));
                float g2 = 2.0f / (1.0f + expf(-v2));
                float g3 = 2.0f / (1.0f + expf(-v3));
                float2 h01 = *(float2*)(Cfd + (size_t)r0 * N + col);
                float2 h23 = *(float2*)(Cfd + (size_t)(r0 + 8) * N + col);
                float sc0 = cs[col], sh0 = cq[col];
                float sc1 = cs[col + 1], sh1 = cq[col + 1];
                *(__half2*)(Chd + (size_t)r0 * N + col) = __floats2half2_rn(
                    fmaxf(h01.x * sc0 + sh0, 0.0f) * g0,
                    fmaxf(h01.y * sc1 + sh1, 0.0f) * g1);
                *(__half2*)(Chd + (size_t)(r0 + 8) * N + col) = __floats2half2_rn(
                    fmaxf(h23.x * sc0 + sh0, 0.0f) * g2,
                    fmaxf(h23.y * sc1 + sh1, 0.0f) * g3);
            }
        }
    }

    if (EPI == 0) {
#pragma unroll
        for (int ni = 0; ni < NI; ni++)
#pragma unroll
            for (int c2 = 0; c2 < 2; c2++) {
                float sv = colS[ni][c2], qv = colQ[ni][c2];
                sv += __shfl_xor_sync(0xffffffffu, sv, 16);
                sv += __shfl_xor_sync(0xffffffffu, sv, 8);
                sv += __shfl_xor_sync(0xffffffffu, sv, 4);
                qv += __shfl_xor_sync(0xffffffffu, qv, 16);
                qv += __shfl_xor_sync(0xffffffffu, qv, 8);
                qv += __shfl_xor_sync(0xffffffffu, qv, 4);
                if (gid == 0) {
                    int c = wn * WN + ni * 8 + 2 * tig + c2;
                    atomicAdd(&cs[c], sv);
                    atomicAdd(&cq[c], qv);
                }
            }
        __syncthreads();
        if (tid < BN) {
            atomicAdd(&sums[d * 256 + bn + tid], cs[tid]);
            atomicAdd(&sums[DNUM * 256 + d * 256 + bn + tid], cq[tid]);
        }
    }
}

// ------------------------- final head -----------------------------------
__global__ void final_kernel(const __half* __restrict__ H,
                             const int* __restrict__ dom,
                             const float* __restrict__ finW,
                             const float* __restrict__ finb,
                             float* __restrict__ out) {
    int warp = (blockIdx.x * blockDim.x + threadIdx.x) >> 5;
    int lane = threadIdx.x & 31;
    if (warp >= BSZ) return;
    int d = dom[warp];
    const __half* h = H + ((size_t)d * BSZ + warp) * 64;
    const float* w = finW + d * 64;
    float s = __half2float(h[lane]) * w[lane] + __half2float(h[lane + 32]) * w[lane + 32];
#pragma unroll
    for (int o = 16; o > 0; o >>= 1) s += __shfl_down_sync(0xffffffffu, s, o);
    if (lane == 0) out[warp] = 1.0f / (1.0f + expf(-(s + finb[d])));
}

// ------------------------- dispatch helper ------------------------------
template <int EPI>
static void launch_gemm(const __half* A, size_t aStride, const __half* Wp,
                        const float* b, float* Cf, __half* Ch, float* sums,
                        const float* bng, const float* bnb, int K, int N) {
    if (N >= 128) {
        constexpr int SM = 5 * (128 * 48 + 128 * 32);    // 51200
        cudaFuncSetAttribute(gemm_tc<128, EPI>, cudaFuncAttributeMaxDynamicSharedMemorySize, SM);
        dim3 grid(BSZ / 128, N / 128, DNUM);
        gemm_tc<128, EPI><<<grid, 256, SM>>>(A, aStride, Wp, b, Cf, Ch, sums, bng, bnb, K, N);
    } else {
        constexpr int SM = 5 * (128 * 48 + 64 * 32);     // 40960
        cudaFuncSetAttribute(gemm_tc<64, EPI>, cudaFuncAttributeMaxDynamicSharedMemorySize, SM);
        dim3 grid(BSZ / 128, N / 64, DNUM);
        gemm_tc<64, EPI><<<grid, 256, SM>>>(A, aStride, Wp, b, Cf, Ch, sums, bng, bnb, K, N);
    }
}

// ------------------------- launch --------------------------------------
extern "C" void kernel_launch(void* const* d_in, const int* in_sizes, int n_in,
                              void* d_out, int out_size) {
    const int*   id_idx    = (const int*)d_in[0];
    const int*   agn_idx   = (const int*)d_in[1];
    const int*   domain_id = (const int*)d_in[2];
    const float* id_tab    = (const float*)d_in[3];
    const float* agn_tab   = (const float*)d_in[4];
    const float* mlp_W[3]  = {(const float*)d_in[5],  (const float*)d_in[13], (const float*)d_in[21]};
    const float* mlp_b[3]  = {(const float*)d_in[6],  (const float*)d_in[14], (const float*)d_in[22]};
    const float* bn_g[3]   = {(const float*)d_in[7],  (const float*)d_in[15], (const float*)d_in[23]};
    const float* bn_b[3]   = {(const float*)d_in[8],  (const float*)d_in[16], (const float*)d_in[24]};
    const float* gW1[3]    = {(const float*)d_in[9],  (const float*)d_in[17], (const float*)d_in[25]};
    const float* gb1[3]    = {(const float*)d_in[10], (const float*)d_in[18], (const float*)d_in[26]};
    const float* gW2[3]    = {(const float*)d_in[11], (const float*)d_in[19], (const float*)d_in[27]};
    const float* gb2[3]    = {(const float*)d_in[12], (const float*)d_in[20], (const float*)d_in[28]};
    const float* finW      = (const float*)d_in[29];
    const float* finb      = (const float*)d_in[30];
    float*       out       = (float*)d_out;

    __half *p_gate_h, *p_g1h, *p_hh, *p_w;
    float *p_hpre, *p_sums;
    cudaGetSymbolAddress((void**)&p_gate_h, g_gate_h);
    cudaGetSymbolAddress((void**)&p_g1h, g_g1h);
    cudaGetSymbolAddress((void**)&p_hh, g_hh);
    cudaGetSymbolAddress((void**)&p_hpre, g_hpre);
    cudaGetSymbolAddress((void**)&p_sums, g_sums3);
    cudaGetSymbolAddress((void**)&p_w, g_wh);

    const int dims[4] = {256, 256, 128, 64};

    // packed fp16 weights
    __half* rW1[3]; __half* rW2[3]; __half* rWm[3];
    size_t off = 0;
    TArgs ta;
    int segi = 0, maxn = 0;
    for (int i = 0; i < 3; i++) {
        int N = dims[i + 1];
        rW1[i] = p_w + off;
        ta.seg[segi++] = {gW1[i], p_w + off, IND, N, DNUM * IND * N};           off += (size_t)DNUM * IND * N;
        rW2[i] = p_w + off;
        ta.seg[segi++] = {gW2[i], p_w + off, N, N, DNUM * N * N};               off += (size_t)DNUM * N * N;
        rWm[i] = p_w + off;
        ta.seg[segi++] = {mlp_W[i], p_w + off, dims[i], N, DNUM * dims[i] * N}; off += (size_t)DNUM * dims[i] * N;
    }
    for (int s = 0; s < 9; s++) if (ta.seg[s].total > maxn) maxn = ta.seg[s].total;

    dim3 rg((maxn + 255) / 256, 9);
    prep_weights<<<rg, 256>>>(ta);

    embed_kernel<<<(BSZ * 64 + 255) / 256, 256>>>(id_idx, agn_idx, id_tab, agn_tab);

    const __half* hprev = nullptr;

    for (int i = 0; i < 3; i++) {
        int Kmlp = dims[i];
        int N    = dims[i + 1];
        float* sums = p_sums + (size_t)i * 2 * DNUM * 256;

        // 1) h_pre = X @ mlp_W + mlp_b (fp32 out + column stats)
        if (i == 0)
            launch_gemm<0>(p_gate_h, 0, rWm[i], mlp_b[i], p_hpre, nullptr, sums, nullptr, nullptr, IND, N);
        else
            launch_gemm<0>(hprev, (size_t)BSZ * Kmlp, rWm[i], mlp_b[i], p_hpre, nullptr, sums, nullptr, nullptr, Kmlp, N);

        // 2) g1 = relu(gate_in @ gW1 + gb1)  (fp16 out)
        launch_gemm<1>(p_gate_h, 0, rW1[i], gb1[i], nullptr, p_g1h, nullptr, nullptr, nullptr, IND, N);

        // 3) gate = 2*sigmoid(g1 @ gW2 + gb2); h = half(relu(bn(h_pre)) * gate)
        launch_gemm<3>(p_g1h, (size_t)BSZ * N, rW2[i], gb2[i], p_hpre, p_hh, sums, bn_g[i], bn_b[i], N, N);

        hprev = p_hh;
    }

    final_kernel<<<BSZ / 8, 256>>>(hprev, domain_id, finW, finb, out);
}

// round 12
// speedup vs baseline: 2.4372x; 1.0248x over previous
#include <cuda_runtime.h>
#include <cuda_fp16.h>
#include <math.h>
#include <stdint.h>

#define BSZ   32768
#define IND   256
#define NFEAT 8
#define EDIM  16
#define VOCAB 100000
#define DNUM  4

// ------------------------- scratch (device globals; no allocs) ----------
__device__ __align__(16) __half g_gate_h[(size_t)BSZ * IND];          // fp16 gate_in
__device__ __align__(16) __half g_g1h[(size_t)DNUM * BSZ * 256];      // fp16 g1
__device__ __align__(16) __half g_hh[(size_t)DNUM * BSZ * 256];       // fp16 h
__device__ float g_hpre[(size_t)DNUM * BSZ * 256];                    // fp32 h_pre
__device__ float g_sums3[3][2 * DNUM * 256];
__device__ __align__(16) __half g_wh[1300000];                        // packed fp16 weights

// ------------------------- helpers --------------------------------------
__device__ __forceinline__ void mma_f16(float c[4], const unsigned a[4],
                                        unsigned b0, unsigned b1) {
    asm volatile(
        "mma.sync.aligned.m16n8k16.row.col.f32.f16.f16.f32 "
        "{%0,%1,%2,%3}, {%4,%5,%6,%7}, {%8,%9}, {%0,%1,%2,%3};"
        : "+f"(c[0]), "+f"(c[1]), "+f"(c[2]), "+f"(c[3])
        : "r"(a[0]), "r"(a[1]), "r"(a[2]), "r"(a[3]), "r"(b0), "r"(b1));
}

__device__ __forceinline__ void ldsm_x4(unsigned r[4], uint32_t addr) {
    asm volatile("ldmatrix.sync.aligned.m8n8.x4.shared.b16 {%0,%1,%2,%3}, [%4];"
                 : "=r"(r[0]), "=r"(r[1]), "=r"(r[2]), "=r"(r[3]) : "r"(addr));
}

__device__ __forceinline__ uint32_t smem_u32(const void* p) {
    uint32_t a;
    asm("{ .reg .u64 t; cvta.to.shared.u64 t, %1; cvt.u32.u64 %0, t; }" : "=r"(a) : "l"(p));
    return a;
}

__device__ __forceinline__ void cp16(uint32_t dst, const void* src) {
    asm volatile("cp.async.cg.shared.global [%0], [%1], 16;" :: "r"(dst), "l"(src));
}
#define CP_COMMIT() asm volatile("cp.async.commit_group;" ::: "memory")
__device__ __forceinline__ void cp_wait_n(int n) {
    if (n <= 0)      asm volatile("cp.async.wait_group 0;" ::: "memory");
    else if (n == 1) asm volatile("cp.async.wait_group 1;" ::: "memory");
    else             asm volatile("cp.async.wait_group 2;" ::: "memory");
}

// ------------------------- weight prep: fp16 + k32 fragment-pack --------
// For k32-pair kp, column n: 32 halves. k = 32kp + 16kt + kr:
//   tig = (kr&7)>>1, pos = (kr&1) | ((kr>>3)<<1)
//   dst half index: ((d*(K/32)+kp)*N + n)*32 + tig*8 + kt*4 + pos
// One LDS.128 per (n, tig) yields kt0 frag (x,y) and kt1 frag (z,w).
struct TSeg { const float* src; __half* dst; int K; int N; int total; };
struct TArgs { TSeg seg[9]; };
__global__ void prep_weights(TArgs a) {
    int s = blockIdx.y;
    int i = blockIdx.x * 256 + threadIdx.x;
    TSeg sg = a.seg[s];
    if (i >= sg.total) return;
    int KN = sg.K * sg.N;
    int d = i / KN, r = i % KN;
    int k = r / sg.N, n = r % sg.N;
    int kp = k >> 5, kk = k & 31;
    int kt = kk >> 4, kr = kk & 15;
    int tig = (kr & 7) >> 1;
    int pos = (kr & 1) | ((kr >> 3) << 1);
    size_t dst = ((size_t)(d * (sg.K >> 5) + kp) * sg.N + n) * 32 + tig * 8 + kt * 4 + pos;
    sg.dst[dst] = __float2half_rn(sg.src[i]);
}

// ------------------------- embedding gather (+ zero sums) ---------------
__global__ void embed_kernel(const int* __restrict__ id_idx,
                             const int* __restrict__ agn_idx,
                             const float* __restrict__ id_tab,
                             const float* __restrict__ agn_tab) {
    int t = blockIdx.x * blockDim.x + threadIdx.x;
    if (t < 3 * 2 * DNUM * 256) ((float*)g_sums3)[t] = 0.0f;
    if (t >= BSZ * 64) return;
    int b = t >> 6;
    int j = (t & 63) << 2;
    const int*   idx = id_idx;
    const float* tab = id_tab;
    int jj = j;
    if (j >= 128) { idx = agn_idx; tab = agn_tab; jj = j - 128; }
    int f = jj >> 4, e = jj & 15;
    int v = idx[b * NFEAT + f];
    float4 val = *(const float4*)(tab + ((size_t)f * VOCAB + v) * EDIM + e);
    __half* p = g_gate_h + (size_t)b * IND + j;
    *(__half2*)(p)     = __floats2half2_rn(val.x, val.y);
    *(__half2*)(p + 2) = __floats2half2_rn(val.z, val.w);
}

// ------------------------- fp16 tensor-core GEMM -------------------------
// acc[d] = A[d] (BSZ x K, fp16) @ W(packed fp16)[d] + bias[d]   (fp32 accum)
// EPI 0: Cf := acc (fp32 h_pre) + column stats into sums
// EPI 1: Ch := half(relu(acc))
// EPI 3: gate = 2*sigmoid(acc); Ch := half(relu(Cf*sc + sh) * gate)
// BM=128, BK=32 (2 x m16n8k16 per frag set), 4-stage cp.async ring.
// 8 warps (4m x 2n), warp tile 32 x (BN/2).
template <int BN, int EPI>
__global__ void __launch_bounds__(256, 2)
gemm_tc(const __half* __restrict__ A, size_t aDomStride,
        const __half* __restrict__ Wp,
        const float* __restrict__ bias,
        float* __restrict__ Cf,
        __half* __restrict__ Ch,
        float* __restrict__ sums,
        const float* __restrict__ bng,
        const float* __restrict__ bnb,
        int K, int N) {
    constexpr int BM = 128, BK = 32;
    constexpr int WN = BN / 2;               // 64 or 32
    constexpr int NI = WN / 8;               // 8 or 4
    constexpr int ASTRIDE = 80;              // bytes per A row (64 data + 16 pad)
    constexpr int ABYTES = BM * ASTRIDE;     // 10240
    constexpr int BBYTES = BN * 64;          // 32 halves per col
    constexpr int SB = ABYTES + BBYTES;
    constexpr int NS = 4;

    extern __shared__ __align__(16) char dynsm[];
    __shared__ float cs[BN], cq[BN];

    int d  = blockIdx.z;
    int bm = blockIdx.x * BM;
    int bn = blockIdx.y * BN;
    const __half* Ad = A + (size_t)d * aDomStride + (size_t)bm * K;
    const __half* Bd = Wp + (size_t)d * K * N + (size_t)bn * 32;
    float*  Cfd = Cf ? Cf + ((size_t)d * BSZ + bm) * N + bn : nullptr;
    __half* Chd = Ch ? Ch + ((size_t)d * BSZ + bm) * N + bn : nullptr;

    int tid  = threadIdx.x;
    int lane = tid & 31, wid = tid >> 5;
    int gid  = lane >> 2, tig = lane & 3;
    int wm   = wid >> 1,  wn  = wid & 1;

    uint32_t sbase = smem_u32(dynsm);

    // ldmatrix lane addressing: row = wm*32 + mi*16 + (lane&15), kcol-16B = lane>>4
    uint32_t lrow = lane & 15;
    uint32_t aFragOff = (wm * 32 + lrow) * ASTRIDE + (lane >> 4) * 16;

    float acc[2][NI][4] = {};

    // staging: A = 128 rows x 64B = 512 cp16 (2/thread); B = BN*4 cp16 (2 or 1/thread)
    auto stage = [&](int kp, int st) {
        uint32_t ab = sbase + st * SB;
#pragma unroll
        for (int i = 0; i < 2; i++) {
            int q = tid + i * 256;
            int row = q >> 2, seg = q & 3;
            cp16(ab + row * ASTRIDE + seg * 16, Ad + (size_t)row * K + kp * 32 + seg * 8);
        }
        uint32_t bb = ab + ABYTES;
        const __half* Bq = Bd + (size_t)kp * N * 32;
#pragma unroll
        for (int i = 0; i < BN / 64; i++) {
            int q = tid + i * 256;
            cp16(bb + q * 16, Bq + q * 8);
        }
        CP_COMMIT();
    };

    const int NCH = K / BK;                  // 8, 4, or 2
    const int npro = NCH < (NS - 1) ? NCH : (NS - 1);
    for (int t = 0; t < npro; t++) stage(t, t);

    int st = 0, sslot = npro;
    for (int c = 0; c < NCH; c++) {
        int pend = NCH - 1 - c; if (pend > NS - 2) pend = NS - 2;
        cp_wait_n(pend);
        __syncthreads();

        uint32_t aS = sbase + st * SB + aFragOff;
        const char* Bbase = dynsm + st * SB + ABYTES;

        // B fragments: one LDS.128 per ni — (x,y) = kt0, (z,w) = kt1
        uint4 bq[NI];
#pragma unroll
        for (int ni = 0; ni < NI; ni++) {
            int cb = wn * WN + ni * 8 + gid;
            bq[ni] = *(const uint4*)(Bbase + cb * 64 + tig * 16);
        }

        // A fragments: 2 x ldmatrix.x4 per mi (kt0 at +0, kt1 at +32)
        unsigned af0[2][4], af1[2][4];
#pragma unroll
        for (int mi = 0; mi < 2; mi++) {
            ldsm_x4(af0[mi], aS + mi * 16 * ASTRIDE);
            ldsm_x4(af1[mi], aS + mi * 16 * ASTRIDE + 32);
        }

#pragma unroll
        for (int mi = 0; mi < 2; mi++)
#pragma unroll
            for (int ni = 0; ni < NI; ni++) {
                mma_f16(acc[mi][ni], af0[mi], bq[ni].x, bq[ni].y);
                mma_f16(acc[mi][ni], af1[mi], bq[ni].z, bq[ni].w);
            }

        if (c + NS - 1 < NCH) {
            stage(c + NS - 1, sslot);
            if (++sslot == NS) sslot = 0;
        }
        if (++st == NS) st = 0;
    }

    if (EPI == 0) {
        if (tid < BN) { cs[tid] = 0.0f; cq[tid] = 0.0f; }
        __syncthreads();
    }
    if (EPI == 3) {
        if (tid < BN) {
            int idxc = d * 256 + bn + tid;
            float mean = sums[idxc] * (1.0f / BSZ);
            float var  = sums[DNUM * 256 + idxc] * (1.0f / BSZ) - mean * mean;
            float sc   = bng[d * N + bn + tid] * rsqrtf(var + 1e-5f);
            cs[tid] = sc;
            cq[tid] = bnb[d * N + bn + tid] - mean * sc;
        }
        __syncthreads();
    }

    float colS[NI][2] = {}, colQ[NI][2] = {};

#pragma unroll
    for (int mi = 0; mi < 2; mi++) {
        int r0 = wm * 32 + mi * 16 + gid;
#pragma unroll
        for (int ni = 0; ni < NI; ni++) {
            int col = wn * WN + ni * 8 + 2 * tig;
            float b0 = bias[d * N + bn + col];
            float b1 = bias[d * N + bn + col + 1];
            float v0 = acc[mi][ni][0] + b0;
            float v1 = acc[mi][ni][1] + b1;
            float v2 = acc[mi][ni][2] + b0;
            float v3 = acc[mi][ni][3] + b1;
            if (EPI == 0) {
                colS[ni][0] += v0 + v2;      colS[ni][1] += v1 + v3;
                colQ[ni][0] += v0 * v0 + v2 * v2;
                colQ[ni][1] += v1 * v1 + v3 * v3;
                *(float2*)(Cfd + (size_t)r0 * N + col)       = make_float2(v0, v1);
                *(float2*)(Cfd + (size_t)(r0 + 8) * N + col) = make_float2(v2, v3);
            }
            if (EPI == 1) {
                *(__half2*)(Chd + (size_t)r0 * N + col) =
                    __floats2half2_rn(fmaxf(v0, 0.0f), fmaxf(v1, 0.0f));
                *(__half2*)(Chd + (size_t)(r0 + 8) * N + col) =
                    __floats2half2_rn(fmaxf(v2, 0.0f), fmaxf(v3, 0.0f));
            }
            if (EPI == 3) {
                float g0 = 2.0f / (1.0f + expf(-v0));
                float g1 = 2.0f / (1.0f + expf(-v1));
                float g2 = 2.0f / (1.0f + expf(-v2));
                float g3 = 2.0f / (1.0f + expf(-v3));
                float2 h01 = *(float2*)(Cfd + (size_t)r0 * N + col);
                float2 h23 = *(float2*)(Cfd + (size_t)(r0 + 8) * N + col);
                float sc0 = cs[col], sh0 = cq[col];
                float sc1 = cs[col + 1], sh1 = cq[col + 1];
                *(__half2*)(Chd + (size_t)r0 * N + col) = __floats2half2_rn(
                    fmaxf(h01.x * sc0 + sh0, 0.0f) * g0,
                    fmaxf(h01.y * sc1 + sh1, 0.0f) * g1);
                *(__half2*)(Chd + (size_t)(r0 + 8) * N + col) = __floats2half2_rn(
                    fmaxf(h23.x * sc0 + sh0, 0.0f) * g2,
                    fmaxf(h23.y * sc1 + sh1, 0.0f) * g3);
            }
        }
    }

    if (EPI == 0) {
#pragma unroll
        for (int ni = 0; ni < NI; ni++)
#pragma unroll
            for (int c2 = 0; c2 < 2; c2++) {
                float sv = colS[ni][c2], qv = colQ[ni][c2];
                sv += __shfl_xor_sync(0xffffffffu, sv, 16);
                sv += __shfl_xor_sync(0xffffffffu, sv, 8);
                sv += __shfl_xor_sync(0xffffffffu, sv, 4);
                qv += __shfl_xor_sync(0xffffffffu, qv, 16);
                qv += __shfl_xor_sync(0xffffffffu, qv, 8);
                qv += __shfl_xor_sync(0xffffffffu, qv, 4);
                if (gid == 0) {
                    int c = wn * WN + ni * 8 + 2 * tig + c2;
                    atomicAdd(&cs[c], sv);
                    atomicAdd(&cq[c], qv);
                }
            }
        __syncthreads();
        if (tid < BN) {
            atomicAdd(&sums[d * 256 + bn + tid], cs[tid]);
            atomicAdd(&sums[DNUM * 256 + d * 256 + bn + tid], cq[tid]);
        }
    }
}

// ------------------------- final head -----------------------------------
__global__ void final_kernel(const __half* __restrict__ H,
                             const int* __restrict__ dom,
                             const float* __restrict__ finW,
                             const float* __restrict__ finb,
                             float* __restrict__ out) {
    int warp = (blockIdx.x * blockDim.x + threadIdx.x) >> 5;
    int lane = threadIdx.x & 31;
    if (warp >= BSZ) return;
    int d = dom[warp];
    const __half* h = H + ((size_t)d * BSZ + warp) * 64;
    const float* w = finW + d * 64;
    float s = __half2float(h[lane]) * w[lane] + __half2float(h[lane + 32]) * w[lane + 32];
#pragma unroll
    for (int o = 16; o > 0; o >>= 1) s += __shfl_down_sync(0xffffffffu, s, o);
    if (lane == 0) out[warp] = 1.0f / (1.0f + expf(-(s + finb[d])));
}

// ------------------------- dispatch helper ------------------------------
template <int EPI>
static void launch_gemm(const __half* A, size_t aStride, const __half* Wp,
                        const float* b, float* Cf, __half* Ch, float* sums,
                        const float* bng, const float* bnb, int K, int N) {
    if (N >= 128) {
        constexpr int SM = 4 * (128 * 80 + 128 * 64);    // 73728
        cudaFuncSetAttribute(gemm_tc<128, EPI>, cudaFuncAttributeMaxDynamicSharedMemorySize, SM);
        dim3 grid(BSZ / 128, N / 128, DNUM);
        gemm_tc<128, EPI><<<grid, 256, SM>>>(A, aStride, Wp, b, Cf, Ch, sums, bng, bnb, K, N);
    } else {
        constexpr int SM = 4 * (128 * 80 + 64 * 64);     // 57344
        cudaFuncSetAttribute(gemm_tc<64, EPI>, cudaFuncAttributeMaxDynamicSharedMemorySize, SM);
        dim3 grid(BSZ / 128, N / 64, DNUM);
        gemm_tc<64, EPI><<<grid, 256, SM>>>(A, aStride, Wp, b, Cf, Ch, sums, bng, bnb, K, N);
    }
}

// ------------------------- launch --------------------------------------
extern "C" void kernel_launch(void* const* d_in, const int* in_sizes, int n_in,
                              void* d_out, int out_size) {
    const int*   id_idx    = (const int*)d_in[0];
    const int*   agn_idx   = (const int*)d_in[1];
    const int*   domain_id = (const int*)d_in[2];
    const float* id_tab    = (const float*)d_in[3];
    const float* agn_tab   = (const float*)d_in[4];
    const float* mlp_W[3]  = {(const float*)d_in[5],  (const float*)d_in[13], (const float*)d_in[21]};
    const float* mlp_b[3]  = {(const float*)d_in[6],  (const float*)d_in[14], (const float*)d_in[22]};
    const float* bn_g[3]   = {(const float*)d_in[7],  (const float*)d_in[15], (const float*)d_in[23]};
    const float* bn_b[3]   = {(const float*)d_in[8],  (const float*)d_in[16], (const float*)d_in[24]};
    const float* gW1[3]    = {(const float*)d_in[9],  (const float*)d_in[17], (const float*)d_in[25]};
    const float* gb1[3]    = {(const float*)d_in[10], (const float*)d_in[18], (const float*)d_in[26]};
    const float* gW2[3]    = {(const float*)d_in[11], (const float*)d_in[19], (const float*)d_in[27]};
    const float* gb2[3]    = {(const float*)d_in[12], (const float*)d_in[20], (const float*)d_in[28]};
    const float* finW      = (const float*)d_in[29];
    const float* finb      = (const float*)d_in[30];
    float*       out       = (float*)d_out;

    __half *p_gate_h, *p_g1h, *p_hh, *p_w;
    float *p_hpre, *p_sums;
    cudaGetSymbolAddress((void**)&p_gate_h, g_gate_h);
    cudaGetSymbolAddress((void**)&p_g1h, g_g1h);
    cudaGetSymbolAddress((void**)&p_hh, g_hh);
    cudaGetSymbolAddress((void**)&p_hpre, g_hpre);
    cudaGetSymbolAddress((void**)&p_sums, g_sums3);
    cudaGetSymbolAddress((void**)&p_w, g_wh);

    const int dims[4] = {256, 256, 128, 64};

    // packed fp16 weights
    __half* rW1[3]; __half* rW2[3]; __half* rWm[3];
    size_t off = 0;
    TArgs ta;
    int segi = 0, maxn = 0;
    for (int i = 0; i < 3; i++) {
        int N = dims[i + 1];
        rW1[i] = p_w + off;
        ta.seg[segi++] = {gW1[i], p_w + off, IND, N, DNUM * IND * N};           off += (size_t)DNUM * IND * N;
        rW2[i] = p_w + off;
        ta.seg[segi++] = {gW2[i], p_w + off, N, N, DNUM * N * N};               off += (size_t)DNUM * N * N;
        rWm[i] = p_w + off;
        ta.seg[segi++] = {mlp_W[i], p_w + off, dims[i], N, DNUM * dims[i] * N}; off += (size_t)DNUM * dims[i] * N;
    }
    for (int s = 0; s < 9; s++) if (ta.seg[s].total > maxn) maxn = ta.seg[s].total;

    dim3 rg((maxn + 255) / 256, 9);
    prep_weights<<<rg, 256>>>(ta);

    embed_kernel<<<(BSZ * 64 + 255) / 256, 256>>>(id_idx, agn_idx, id_tab, agn_tab);

    const __half* hprev = nullptr;

    for (int i = 0; i < 3; i++) {
        int Kmlp = dims[i];
        int N    = dims[i + 1];
        float* sums = p_sums + (size_t)i * 2 * DNUM * 256;

        // 1) h_pre = X @ mlp_W + mlp_b (fp32 out + column stats)
        if (i == 0)
            launch_gemm<0>(p_gate_h, 0, rWm[i], mlp_b[i], p_hpre, nullptr, sums, nullptr, nullptr, IND, N);
        else
            launch_gemm<0>(hprev, (size_t)BSZ * Kmlp, rWm[i], mlp_b[i], p_hpre, nullptr, sums, nullptr, nullptr, Kmlp, N);

        // 2) g1 = relu(gate_in @ gW1 + gb1)  (fp16 out)
        launch_gemm<1>(p_gate_h, 0, rW1[i], gb1[i], nullptr, p_g1h, nullptr, nullptr, nullptr, IND, N);

        // 3) gate = 2*sigmoid(g1 @ gW2 + gb2); h = half(relu(bn(h_pre)) * gate)
        launch_gemm<3>(p_g1h, (size_t)BSZ * N, rW2[i], gb2[i], p_hpre, p_hh, sums, bn_g[i], bn_b[i], N, N);

        hprev = p_hh;
    }

    final_kernel<<<BSZ / 8, 256>>>(hprev, domain_id, finW, finb, out);
}

// round 13
// speedup vs baseline: 2.4456x; 1.0034x over previous
#include <cuda_runtime.h>
#include <cuda_fp16.h>
#include <math.h>
#include <stdint.h>

#define BSZ   32768
#define IND   256
#define NFEAT 8
#define EDIM  16
#define VOCAB 100000
#define DNUM  4

// ------------------------- scratch (device globals; no allocs) ----------
__device__ __align__(16) __half g_gate_h[(size_t)BSZ * IND];          // fp16 gate_in
__device__ __align__(16) __half g_g1h[(size_t)DNUM * BSZ * 448];      // fp16 g1 (per-layer)
__device__ __align__(16) __half g_hh[(size_t)DNUM * BSZ * 256];       // fp16 h
__device__ float g_hpre[(size_t)DNUM * BSZ * 256];                    // fp32 h_pre
__device__ float g_sums3[3][2 * DNUM * 256];
__device__ __align__(16) __half g_wh[1300000];                        // packed fp16 weights

// ------------------------- helpers --------------------------------------
__device__ __forceinline__ void mma_f16(float c[4], const unsigned a[4],
                                        unsigned b0, unsigned b1) {
    asm volatile(
        "mma.sync.aligned.m16n8k16.row.col.f32.f16.f16.f32 "
        "{%0,%1,%2,%3}, {%4,%5,%6,%7}, {%8,%9}, {%0,%1,%2,%3};"
        : "+f"(c[0]), "+f"(c[1]), "+f"(c[2]), "+f"(c[3])
        : "r"(a[0]), "r"(a[1]), "r"(a[2]), "r"(a[3]), "r"(b0), "r"(b1));
}

__device__ __forceinline__ void ldsm_x4(unsigned r[4], uint32_t addr) {
    asm volatile("ldmatrix.sync.aligned.m8n8.x4.shared.b16 {%0,%1,%2,%3}, [%4];"
                 : "=r"(r[0]), "=r"(r[1]), "=r"(r[2]), "=r"(r[3]) : "r"(addr));
}

__device__ __forceinline__ uint32_t smem_u32(const void* p) {
    uint32_t a;
    asm("{ .reg .u64 t; cvta.to.shared.u64 t, %1; cvt.u32.u64 %0, t; }" : "=r"(a) : "l"(p));
    return a;
}

__device__ __forceinline__ void cp16(uint32_t dst, const void* src) {
    asm volatile("cp.async.cg.shared.global [%0], [%1], 16;" :: "r"(dst), "l"(src));
}
#define CP_COMMIT() asm volatile("cp.async.commit_group;" ::: "memory")
__device__ __forceinline__ void cp_wait_n(int n) {
    if (n <= 0)      asm volatile("cp.async.wait_group 0;" ::: "memory");
    else if (n == 1) asm volatile("cp.async.wait_group 1;" ::: "memory");
    else             asm volatile("cp.async.wait_group 2;" ::: "memory");
}

// ------------------------- weight prep: fp16 + k32 fragment-pack --------
// For k32-pair kp, column n: 32 halves. k = 32kp + 16kt + kr:
//   tig = (kr&7)>>1, pos = (kr&1) | ((kr>>3)<<1)
//   dst half index: ((d*(K/32)+kp)*N + n)*32 + tig*8 + kt*4 + pos
struct TSeg { const float* src; __half* dst; int K; int N; int total; };
struct TArgs { TSeg seg[9]; };
__global__ void prep_weights(TArgs a) {
    int s = blockIdx.y;
    int i = blockIdx.x * 256 + threadIdx.x;
    TSeg sg = a.seg[s];
    if (i >= sg.total) return;
    int KN = sg.K * sg.N;
    int d = i / KN, r = i % KN;
    int k = r / sg.N, n = r % sg.N;
    int kp = k >> 5, kk = k & 31;
    int kt = kk >> 4, kr = kk & 15;
    int tig = (kr & 7) >> 1;
    int pos = (kr & 1) | ((kr >> 3) << 1);
    size_t dst = ((size_t)(d * (sg.K >> 5) + kp) * sg.N + n) * 32 + tig * 8 + kt * 4 + pos;
    sg.dst[dst] = __float2half_rn(sg.src[i]);
}

// ------------------------- embedding gather (+ zero sums) ---------------
__global__ void embed_kernel(const int* __restrict__ id_idx,
                             const int* __restrict__ agn_idx,
                             const float* __restrict__ id_tab,
                             const float* __restrict__ agn_tab) {
    int t = blockIdx.x * blockDim.x + threadIdx.x;
    if (t < 3 * 2 * DNUM * 256) ((float*)g_sums3)[t] = 0.0f;
    if (t >= BSZ * 64) return;
    int b = t >> 6;
    int j = (t & 63) << 2;
    const int*   idx = id_idx;
    const float* tab = id_tab;
    int jj = j;
    if (j >= 128) { idx = agn_idx; tab = agn_tab; jj = j - 128; }
    int f = jj >> 4, e = jj & 15;
    int v = idx[b * NFEAT + f];
    float4 val = *(const float4*)(tab + ((size_t)f * VOCAB + v) * EDIM + e);
    __half* p = g_gate_h + (size_t)b * IND + j;
    *(__half2*)(p)     = __floats2half2_rn(val.x, val.y);
    *(__half2*)(p + 2) = __floats2half2_rn(val.z, val.w);
}

// ------------------------- fp16 tensor-core GEMM -------------------------
// acc[d] = A[d] (BSZ x K, fp16) @ W(packed fp16)[d] + bias[d]   (fp32 accum)
// EPI 0: Cf := acc (fp32 h_pre) + column stats into sums
// EPI 1: Ch := half(relu(acc))
// EPI 3: gate = 2*sigmoid(acc); Ch := half(relu(Cf*sc + sh) * gate)
// BM=128, BK=32, 4-stage cp.async ring. 8 warps (4m x 2n), warp tile 32 x (BN/2).
template <int BN, int EPI>
__global__ void __launch_bounds__(256, 2)
gemm_tc(const __half* __restrict__ A, size_t aDomStride,
        const __half* __restrict__ Wp,
        const float* __restrict__ bias,
        float* __restrict__ Cf,
        __half* __restrict__ Ch,
        float* __restrict__ sums,
        const float* __restrict__ bng,
        const float* __restrict__ bnb,
        int K, int N) {
    constexpr int BM = 128, BK = 32;
    constexpr int WN = BN / 2;               // 64 or 32
    constexpr int NI = WN / 8;               // 8 or 4
    constexpr int ASTRIDE = 80;              // bytes per A row (64 data + 16 pad)
    constexpr int ABYTES = BM * ASTRIDE;     // 10240
    constexpr int BBYTES = BN * 64;          // 32 halves per col
    constexpr int SB = ABYTES + BBYTES;
    constexpr int NS = 4;

    extern __shared__ __align__(16) char dynsm[];
    __shared__ float cs[BN], cq[BN];

    int d  = blockIdx.z;
    int bm = blockIdx.x * BM;
    int bn = blockIdx.y * BN;
    const __half* Ad = A + (size_t)d * aDomStride + (size_t)bm * K;
    const __half* Bd = Wp + (size_t)d * K * N + (size_t)bn * 32;
    float*  Cfd = Cf ? Cf + ((size_t)d * BSZ + bm) * N + bn : nullptr;
    __half* Chd = Ch ? Ch + ((size_t)d * BSZ + bm) * N + bn : nullptr;

    int tid  = threadIdx.x;
    int lane = tid & 31, wid = tid >> 5;
    int gid  = lane >> 2, tig = lane & 3;
    int wm   = wid >> 1,  wn  = wid & 1;

    uint32_t sbase = smem_u32(dynsm);
    uint32_t lrow = lane & 15;
    uint32_t aFragOff = (wm * 32 + lrow) * ASTRIDE + (lane >> 4) * 16;

    float acc[2][NI][4] = {};

    auto stage = [&](int kp, int st) {
        uint32_t ab = sbase + st * SB;
#pragma unroll
        for (int i = 0; i < 2; i++) {
            int q = tid + i * 256;
            int row = q >> 2, seg = q & 3;
            cp16(ab + row * ASTRIDE + seg * 16, Ad + (size_t)row * K + kp * 32 + seg * 8);
        }
        uint32_t bb = ab + ABYTES;
        const __half* Bq = Bd + (size_t)kp * N * 32;
#pragma unroll
        for (int i = 0; i < BN / 64; i++) {
            int q = tid + i * 256;
            cp16(bb + q * 16, Bq + q * 8);
        }
        CP_COMMIT();
    };

    const int NCH = K / BK;                  // 8, 4, or 2
    const int npro = NCH < (NS - 1) ? NCH : (NS - 1);
    for (int t = 0; t < npro; t++) stage(t, t);

    int st = 0, sslot = npro;
    for (int c = 0; c < NCH; c++) {
        int pend = NCH - 1 - c; if (pend > NS - 2) pend = NS - 2;
        cp_wait_n(pend);
        __syncthreads();

        uint32_t aS = sbase + st * SB + aFragOff;
        const char* Bbase = dynsm + st * SB + ABYTES;

        uint4 bq[NI];
#pragma unroll
        for (int ni = 0; ni < NI; ni++) {
            int cb = wn * WN + ni * 8 + gid;
            bq[ni] = *(const uint4*)(Bbase + cb * 64 + tig * 16);
        }

        unsigned af0[2][4], af1[2][4];
#pragma unroll
        for (int mi = 0; mi < 2; mi++) {
            ldsm_x4(af0[mi], aS + mi * 16 * ASTRIDE);
            ldsm_x4(af1[mi], aS + mi * 16 * ASTRIDE + 32);
        }

#pragma unroll
        for (int mi = 0; mi < 2; mi++)
#pragma unroll
            for (int ni = 0; ni < NI; ni++) {
                mma_f16(acc[mi][ni], af0[mi], bq[ni].x, bq[ni].y);
                mma_f16(acc[mi][ni], af1[mi], bq[ni].z, bq[ni].w);
            }

        if (c + NS - 1 < NCH) {
            stage(c + NS - 1, sslot);
            if (++sslot == NS) sslot = 0;
        }
        if (++st == NS) st = 0;
    }

    if (EPI == 0) {
        if (tid < BN) { cs[tid] = 0.0f; cq[tid] = 0.0f; }
        __syncthreads();
    }
    if (EPI == 3) {
        if (tid < BN) {
            int idxc = d * 256 + bn + tid;
            float mean = sums[idxc] * (1.0f / BSZ);
            float var  = sums[DNUM * 256 + idxc] * (1.0f / BSZ) - mean * mean;
            float sc   = bng[d * N + bn + tid] * rsqrtf(var + 1e-5f);
            cs[tid] = sc;
            cq[tid] = bnb[d * N + bn + tid] - mean * sc;
        }
        __syncthreads();
    }

    float colS[NI][2] = {}, colQ[NI][2] = {};

#pragma unroll
    for (int mi = 0; mi < 2; mi++) {
        int r0 = wm * 32 + mi * 16 + gid;
#pragma unroll
        for (int ni = 0; ni < NI; ni++) {
            int col = wn * WN + ni * 8 + 2 * tig;
            float b0 = bias[d * N + bn + col];
            float b1 = bias[d * N + bn + col + 1];
            float v0 = acc[mi][ni][0] + b0;
            float v1 = acc[mi][ni][1] + b1;
            float v2 = acc[mi][ni][2] + b0;
            float v3 = acc[mi][ni][3] + b1;
            if (EPI == 0) {
                colS[ni][0] += v0 + v2;      colS[ni][1] += v1 + v3;
                colQ[ni][0] += v0 * v0 + v2 * v2;
                colQ[ni][1] += v1 * v1 + v3 * v3;
                *(float2*)(Cfd + (size_t)r0 * N + col)       = make_float2(v0, v1);
                *(float2*)(Cfd + (size_t)(r0 + 8) * N + col) = make_float2(v2, v3);
            }
            if (EPI == 1) {
                *(__half2*)(Chd + (size_t)r0 * N + col) =
                    __floats2half2_rn(fmaxf(v0, 0.0f), fmaxf(v1, 0.0f));
                *(__half2*)(Chd + (size_t)(r0 + 8) * N + col) =
                    __floats2half2_rn(fmaxf(v2, 0.0f), fmaxf(v3, 0.0f));
            }
            if (EPI == 3) {
                float g0 = 2.0f / (1.0f + expf(-v0));
                float g1 = 2.0f / (1.0f + expf(-v1));
                float g2 = 2.0f / (1.0f + expf(-v2));
                float g3 = 2.0f / (1.0f + expf(-v3));
                float2 h01 = *(float2*)(Cfd + (size_t)r0 * N + col);
                float2 h23 = *(float2*)(Cfd + (size_t)(r0 + 8) * N + col);
                float sc0 = cs[col], sh0 = cq[col];
                float sc1 = cs[col + 1], sh1 = cq[col + 1];
                *(__half2*)(Chd + (size_t)r0 * N + col) = __floats2half2_rn(
                    fmaxf(h01.x * sc0 + sh0, 0.0f) * g0,
                    fmaxf(h01.y * sc1 + sh1, 0.0f) * g1);
                *(__half2*)(Chd + (size_t)(r0 + 8) * N + col) = __floats2half2_rn(
                    fmaxf(h23.x * sc0 + sh0, 0.0f) * g2,
                    fmaxf(h23.y * sc1 + sh1, 0.0f) * g3);
            }
        }
    }

    if (EPI == 0) {
#pragma unroll
        for (int ni = 0; ni < NI; ni++)
#pragma unroll
            for (int c2 = 0; c2 < 2; c2++) {
                float sv = colS[ni][c2], qv = colQ[ni][c2];
                sv += __shfl_xor_sync(0xffffffffu, sv, 16);
                sv += __shfl_xor_sync(0xffffffffu, sv, 8);
                sv += __shfl_xor_sync(0xffffffffu, sv, 4);
                qv += __shfl_xor_sync(0xffffffffu, qv, 16);
                qv += __shfl_xor_sync(0xffffffffu, qv, 8);
                qv += __shfl_xor_sync(0xffffffffu, qv, 4);
                if (gid == 0) {
                    int c = wn * WN + ni * 8 + 2 * tig + c2;
                    atomicAdd(&cs[c], sv);
                    atomicAdd(&cq[c], qv);
                }
            }
        __syncthreads();
        if (tid < BN) {
            atomicAdd(&sums[d * 256 + bn + tid], cs[tid]);
            atomicAdd(&sums[DNUM * 256 + d * 256 + bn + tid], cq[tid]);
        }
    }
}

// ------------------------- final head -----------------------------------
__global__ void final_kernel(const __half* __restrict__ H,
                             const int* __restrict__ dom,
                             const float* __restrict__ finW,
                             const float* __restrict__ finb,
                             float* __restrict__ out) {
    int warp = (blockIdx.x * blockDim.x + threadIdx.x) >> 5;
    int lane = threadIdx.x & 31;
    if (warp >= BSZ) return;
    int d = dom[warp];
    const __half* h = H + ((size_t)d * BSZ + warp) * 64;
    const float* w = finW + d * 64;
    float s = __half2float(h[lane]) * w[lane] + __half2float(h[lane + 32]) * w[lane + 32];
#pragma unroll
    for (int o = 16; o > 0; o >>= 1) s += __shfl_down_sync(0xffffffffu, s, o);
    if (lane == 0) out[warp] = 1.0f / (1.0f + expf(-(s + finb[d])));
}

// ------------------------- dispatch helper ------------------------------
template <int EPI>
static void launch_gemm(cudaStream_t st, const __half* A, size_t aStride,
                        const __half* Wp, const float* b, float* Cf, __half* Ch,
                        float* sums, const float* bng, const float* bnb, int K, int N) {
    if (N >= 128) {
        constexpr int SM = 4 * (128 * 80 + 128 * 64);    // 73728
        cudaFuncSetAttribute(gemm_tc<128, EPI>, cudaFuncAttributeMaxDynamicSharedMemorySize, SM);
        dim3 grid(BSZ / 128, N / 128, DNUM);
        gemm_tc<128, EPI><<<grid, 256, SM, st>>>(A, aStride, Wp, b, Cf, Ch, sums, bng, bnb, K, N);
    } else {
        constexpr int SM = 4 * (128 * 80 + 64 * 64);     // 57344
        cudaFuncSetAttribute(gemm_tc<64, EPI>, cudaFuncAttributeMaxDynamicSharedMemorySize, SM);
        dim3 grid(BSZ / 128, N / 64, DNUM);
        gemm_tc<64, EPI><<<grid, 256, SM, st>>>(A, aStride, Wp, b, Cf, Ch, sums, bng, bnb, K, N);
    }
}

// ------------------------- launch --------------------------------------
extern "C" void kernel_launch(void* const* d_in, const int* in_sizes, int n_in,
                              void* d_out, int out_size) {
    const int*   id_idx    = (const int*)d_in[0];
    const int*   agn_idx   = (const int*)d_in[1];
    const int*   domain_id = (const int*)d_in[2];
    const float* id_tab    = (const float*)d_in[3];
    const float* agn_tab   = (const float*)d_in[4];
    const float* mlp_W[3]  = {(const float*)d_in[5],  (const float*)d_in[13], (const float*)d_in[21]};
    const float* mlp_b[3]  = {(const float*)d_in[6],  (const float*)d_in[14], (const float*)d_in[22]};
    const float* bn_g[3]   = {(const float*)d_in[7],  (const float*)d_in[15], (const float*)d_in[23]};
    const float* bn_b[3]   = {(const float*)d_in[8],  (const float*)d_in[16], (const float*)d_in[24]};
    const float* gW1[3]    = {(const float*)d_in[9],  (const float*)d_in[17], (const float*)d_in[25]};
    const float* gb1[3]    = {(const float*)d_in[10], (const float*)d_in[18], (const float*)d_in[26]};
    const float* gW2[3]    = {(const float*)d_in[11], (const float*)d_in[19], (const float*)d_in[27]};
    const float* gb2[3]    = {(const float*)d_in[12], (const float*)d_in[20], (const float*)d_in[28]};
    const float* finW      = (const float*)d_in[29];
    const float* finb      = (const float*)d_in[30];
    float*       out       = (float*)d_out;

    __half *p_gate_h, *p_g1h, *p_hh, *p_w;
    float *p_hpre, *p_sums;
    cudaGetSymbolAddress((void**)&p_gate_h, g_gate_h);
    cudaGetSymbolAddress((void**)&p_g1h, g_g1h);
    cudaGetSymbolAddress((void**)&p_hh, g_hh);
    cudaGetSymbolAddress((void**)&p_hpre, g_hpre);
    cudaGetSymbolAddress((void**)&p_sums, g_sums3);
    cudaGetSymbolAddress((void**)&p_w, g_wh);

    // one-time host objects (no device memory involved)
    static cudaStream_t s1 = nullptr;
    static cudaEvent_t evStart, evEmbed, evG1[3];
    if (!s1) {
        cudaStreamCreateWithFlags(&s1, cudaStreamNonBlocking);
        cudaEventCreateWithFlags(&evStart, cudaEventDisableTiming);
        cudaEventCreateWithFlags(&evEmbed, cudaEventDisableTiming);
        for (int i = 0; i < 3; i++) cudaEventCreateWithFlags(&evG1[i], cudaEventDisableTiming);
    }

    const int dims[4] = {256, 256, 128, 64};

    // packed fp16 weights
    __half* rW1[3]; __half* rW2[3]; __half* rWm[3];
    size_t off = 0;
    TArgs ta;
    int segi = 0, maxn = 0;
    for (int i = 0; i < 3; i++) {
        int N = dims[i + 1];
        rW1[i] = p_w + off;
        ta.seg[segi++] = {gW1[i], p_w + off, IND, N, DNUM * IND * N};           off += (size_t)DNUM * IND * N;
        rW2[i] = p_w + off;
        ta.seg[segi++] = {gW2[i], p_w + off, N, N, DNUM * N * N};               off += (size_t)DNUM * N * N;
        rWm[i] = p_w + off;
        ta.seg[segi++] = {mlp_W[i], p_w + off, dims[i], N, DNUM * dims[i] * N}; off += (size_t)DNUM * dims[i] * N;
    }
    for (int s = 0; s < 9; s++) if (ta.seg[s].total > maxn) maxn = ta.seg[s].total;

    // per-layer g1 buffers
    __half* g1buf[3];
    size_t goff = 0;
    for (int i = 0; i < 3; i++) {
        g1buf[i] = p_g1h + goff;
        goff += (size_t)DNUM * BSZ * dims[i + 1];
    }

    // ---- fork: side stream does prep + all three gW1 GEMMs -------------
    cudaEventRecord(evStart, 0);
    cudaStreamWaitEvent(s1, evStart, 0);

    dim3 rg((maxn + 255) / 256, 9);
    prep_weights<<<rg, 256, 0, s1>>>(ta);

    embed_kernel<<<(BSZ * 64 + 255) / 256, 256>>>(id_idx, agn_idx, id_tab, agn_tab);
    cudaEventRecord(evEmbed, 0);
    cudaStreamWaitEvent(s1, evEmbed, 0);

    for (int i = 0; i < 3; i++) {
        launch_gemm<1>(s1, p_gate_h, 0, rW1[i], gb1[i], nullptr, g1buf[i],
                       nullptr, nullptr, nullptr, IND, dims[i + 1]);
        cudaEventRecord(evG1[i], s1);
    }

    // ---- main stream: embed -> (mlp -> gW2)x3 -> final -----------------
    // main also needs prep done before mlp0 (weights): evG1 path covers gW1;
    // for mlp weights, wait on a prep-completion via s1 order: prep precedes
    // gW1_0, so evG1[0] implies prep done — but mlp0 runs BEFORE that wait.
    // So explicitly order prep before mlp0:
    cudaEventRecord(evStart, s1);            // after prep (s1 in-order: prep queued first)
    // NOTE: evStart reused — recorded on s1 right after gW1 launches were queued;
    // but we need prep-only. s1 order: prep, gW1_0.. so record AFTER prep needs
    // a separate point. Simplest correct: make main wait evG1[0]? too late.
    // Instead: wait on nothing — order prep on stream 0 BEFORE fork would serialize.
    // Correct fix: main waits on an event recorded between prep and gW1_0.
    // (handled below with evPrep)
    const __half* hprev = nullptr;

    static cudaEvent_t evPrep = nullptr;
    if (!evPrep) cudaEventCreateWithFlags(&evPrep, cudaEventDisableTiming);
    // re-queue: record prep-done event. Events can be recorded once per capture;
    // we recorded evStart twice above which is legal (overwrites). For clarity,
    // record evPrep on s1 now — s1 is in-order, so evPrep fires after gW1 launches
    // queued so far. To keep mlp0 early, instead rely on: prep is the FIRST s1 op;
    // main's mlp0 must wait only for prep. We therefore record evPrep immediately
    // after prep at queue time — done via the block below on first pass.
    // (Restructured: see sequence — evPrep recorded right after prep_weights.)

    // --- actual corrected sequence is below; the above comments document intent.

    for (int i = 0; i < 3; i++) {
        int Kmlp = dims[i];
        int N    = dims[i + 1];
        float* sums = p_sums + (size_t)i * 2 * DNUM * 256;

        if (i == 0) {
            // mlp0 needs prep(weights) + embed; prep is on s1. Wait on evG1[0]
            // would over-serialize; instead wait on evPrepDone recorded on s1
            // immediately after prep (see fork section rework below).
            cudaStreamWaitEvent(0, evStart, 0);   // evStart last recorded on s1 after gW1 queue = prep+gW1 all queued; conservative ordering
            launch_gemm<0>(0, p_gate_h, 0, rWm[i], mlp_b[i], p_hpre, nullptr, sums, nullptr, nullptr, IND, N);
        } else {
            launch_gemm<0>(0, hprev, (size_t)BSZ * Kmlp, rWm[i], mlp_b[i], p_hpre, nullptr, sums, nullptr, nullptr, Kmlp, N);
        }

        cudaStreamWaitEvent(0, evG1[i], 0);
        launch_gemm<3>(0, g1buf[i], (size_t)BSZ * N, rW2[i], gb2[i], p_hpre, p_hh, sums, bn_g[i], bn_b[i], N, N);

        hprev = p_hh;
    }

    final_kernel<<<BSZ / 8, 256>>>(hprev, domain_id, finW, finb, out);
}

// round 14
// speedup vs baseline: 2.5242x; 1.0322x over previous
#include <cuda_runtime.h>
#include <cuda_fp16.h>
#include <math.h>
#include <stdint.h>

#define BSZ   32768
#define IND   256
#define NFEAT 8
#define EDIM  16
#define VOCAB 100000
#define DNUM  4

// ------------------------- scratch (device globals; no allocs) ----------
__device__ __align__(16) __half g_gate_h[(size_t)BSZ * IND];          // fp16 gate_in
__device__ __align__(16) __half g_g1h[(size_t)DNUM * BSZ * 448];      // fp16 g1 (per-layer)
__device__ __align__(16) __half g_hh[(size_t)DNUM * BSZ * 256];       // fp16 h
__device__ float g_hpre[(size_t)DNUM * BSZ * 256];                    // fp32 h_pre
__device__ float g_sums3[3][2 * DNUM * 256];
__device__ __align__(16) __half g_wh[1300000];                        // packed fp16 weights

// ------------------------- helpers --------------------------------------
__device__ __forceinline__ void mma_f16(float c[4], const unsigned a[4],
                                        unsigned b0, unsigned b1) {
    asm volatile(
        "mma.sync.aligned.m16n8k16.row.col.f32.f16.f16.f32 "
        "{%0,%1,%2,%3}, {%4,%5,%6,%7}, {%8,%9}, {%0,%1,%2,%3};"
        : "+f"(c[0]), "+f"(c[1]), "+f"(c[2]), "+f"(c[3])
        : "r"(a[0]), "r"(a[1]), "r"(a[2]), "r"(a[3]), "r"(b0), "r"(b1));
}

__device__ __forceinline__ void ldsm_x4(unsigned r[4], uint32_t addr) {
    asm volatile("ldmatrix.sync.aligned.m8n8.x4.shared.b16 {%0,%1,%2,%3}, [%4];"
                 : "=r"(r[0]), "=r"(r[1]), "=r"(r[2]), "=r"(r[3]) : "r"(addr));
}

__device__ __forceinline__ uint32_t smem_u32(const void* p) {
    uint32_t a;
    asm("{ .reg .u64 t; cvta.to.shared.u64 t, %1; cvt.u32.u64 %0, t; }" : "=r"(a) : "l"(p));
    return a;
}

__device__ __forceinline__ void cp16(uint32_t dst, const void* src) {
    asm volatile("cp.async.cg.shared.global [%0], [%1], 16;" :: "r"(dst), "l"(src));
}
#define CP_COMMIT() asm volatile("cp.async.commit_group;" ::: "memory")
__device__ __forceinline__ void cp_wait_n(int n) {
    if (n <= 0)      asm volatile("cp.async.wait_group 0;" ::: "memory");
    else if (n == 1) asm volatile("cp.async.wait_group 1;" ::: "memory");
    else             asm volatile("cp.async.wait_group 2;" ::: "memory");
}

// ------------------------- weight prep: fp16 + k32 fragment-pack --------
// For k32-pair kp, column n: 32 halves. k = 32kp + 16kt + kr:
//   tig = (kr&7)>>1, pos = (kr&1) | ((kr>>3)<<1)
//   dst half index: ((d*(K/32)+kp)*N + n)*32 + tig*8 + kt*4 + pos
struct TSeg { const float* src; __half* dst; int K; int N; int total; };
struct TArgs { TSeg seg[9]; };
__global__ void prep_weights(TArgs a) {
    int s = blockIdx.y;
    int i = blockIdx.x * 256 + threadIdx.x;
    TSeg sg = a.seg[s];
    if (i >= sg.total) return;
    int KN = sg.K * sg.N;
    int d = i / KN, r = i % KN;
    int k = r / sg.N, n = r % sg.N;
    int kp = k >> 5, kk = k & 31;
    int kt = kk >> 4, kr = kk & 15;
    int tig = (kr & 7) >> 1;
    int pos = (kr & 1) | ((kr >> 3) << 1);
    size_t dst = ((size_t)(d * (sg.K >> 5) + kp) * sg.N + n) * 32 + tig * 8 + kt * 4 + pos;
    sg.dst[dst] = __float2half_rn(sg.src[i]);
}

// ------------------------- embedding gather (+ zero sums) ---------------
__global__ void embed_kernel(const int* __restrict__ id_idx,
                             const int* __restrict__ agn_idx,
                             const float* __restrict__ id_tab,
                             const float* __restrict__ agn_tab) {
    int t = blockIdx.x * blockDim.x + threadIdx.x;
    if (t < 3 * 2 * DNUM * 256) ((float*)g_sums3)[t] = 0.0f;
    if (t >= BSZ * 64) return;
    int b = t >> 6;
    int j = (t & 63) << 2;
    const int*   idx = id_idx;
    const float* tab = id_tab;
    int jj = j;
    if (j >= 128) { idx = agn_idx; tab = agn_tab; jj = j - 128; }
    int f = jj >> 4, e = jj & 15;
    int v = idx[b * NFEAT + f];
    float4 val = *(const float4*)(tab + ((size_t)f * VOCAB + v) * EDIM + e);
    __half* p = g_gate_h + (size_t)b * IND + j;
    *(__half2*)(p)     = __floats2half2_rn(val.x, val.y);
    *(__half2*)(p + 2) = __floats2half2_rn(val.z, val.w);
}

// ------------------------- fp16 tensor-core GEMM -------------------------
// acc[d] = A[d] (BSZ x K, fp16) @ W(packed fp16)[d] + bias[d]   (fp32 accum)
// EPI 0: Cf := acc (fp32 h_pre) + column stats into sums
// EPI 1: Ch := half(relu(acc))
// EPI 3: gate = 2*sigmoid(acc); Ch := half(relu(Cf*sc + sh) * gate)
// BM=128, BK=32, 4-stage cp.async ring. 8 warps (4m x 2n), warp tile 32 x (BN/2).
template <int BN, int EPI>
__global__ void __launch_bounds__(256, 2)
gemm_tc(const __half* __restrict__ A, size_t aDomStride,
        const __half* __restrict__ Wp,
        const float* __restrict__ bias,
        float* __restrict__ Cf,
        __half* __restrict__ Ch,
        float* __restrict__ sums,
        const float* __restrict__ bng,
        const float* __restrict__ bnb,
        int K, int N) {
    constexpr int BM = 128, BK = 32;
    constexpr int WN = BN / 2;               // 64 or 32
    constexpr int NI = WN / 8;               // 8 or 4
    constexpr int ASTRIDE = 80;              // bytes per A row (64 data + 16 pad)
    constexpr int ABYTES = BM * ASTRIDE;     // 10240
    constexpr int BBYTES = BN * 64;          // 32 halves per col
    constexpr int SB = ABYTES + BBYTES;
    constexpr int NS = 4;

    extern __shared__ __align__(16) char dynsm[];
    __shared__ float cs[BN], cq[BN];

    int d  = blockIdx.z;
    int bm = blockIdx.x * BM;
    int bn = blockIdx.y * BN;
    const __half* Ad = A + (size_t)d * aDomStride + (size_t)bm * K;
    const __half* Bd = Wp + (size_t)d * K * N + (size_t)bn * 32;
    float*  Cfd = Cf ? Cf + ((size_t)d * BSZ + bm) * N + bn : nullptr;
    __half* Chd = Ch ? Ch + ((size_t)d * BSZ + bm) * N + bn : nullptr;

    int tid  = threadIdx.x;
    int lane = tid & 31, wid = tid >> 5;
    int gid  = lane >> 2, tig = lane & 3;
    int wm   = wid >> 1,  wn  = wid & 1;

    uint32_t sbase = smem_u32(dynsm);
    uint32_t lrow = lane & 15;
    uint32_t aFragOff = (wm * 32 + lrow) * ASTRIDE + (lane >> 4) * 16;

    float acc[2][NI][4] = {};

    auto stage = [&](int kp, int st) {
        uint32_t ab = sbase + st * SB;
#pragma unroll
        for (int i = 0; i < 2; i++) {
            int q = tid + i * 256;
            int row = q >> 2, seg = q & 3;
            cp16(ab + row * ASTRIDE + seg * 16, Ad + (size_t)row * K + kp * 32 + seg * 8);
        }
        uint32_t bb = ab + ABYTES;
        const __half* Bq = Bd + (size_t)kp * N * 32;
#pragma unroll
        for (int i = 0; i < BN / 64; i++) {
            int q = tid + i * 256;
            cp16(bb + q * 16, Bq + q * 8);
        }
        CP_COMMIT();
    };

    const int NCH = K / BK;                  // 8, 4, or 2
    const int npro = NCH < (NS - 1) ? NCH : (NS - 1);
    for (int t = 0; t < npro; t++) stage(t, t);

    int st = 0, sslot = npro;
    for (int c = 0; c < NCH; c++) {
        int pend = NCH - 1 - c; if (pend > NS - 2) pend = NS - 2;
        cp_wait_n(pend);
        __syncthreads();

        uint32_t aS = sbase + st * SB + aFragOff;
        const char* Bbase = dynsm + st * SB + ABYTES;

        uint4 bq[NI];
#pragma unroll
        for (int ni = 0; ni < NI; ni++) {
            int cb = wn * WN + ni * 8 + gid;
            bq[ni] = *(const uint4*)(Bbase + cb * 64 + tig * 16);
        }

        unsigned af0[2][4], af1[2][4];
#pragma unroll
        for (int mi = 0; mi < 2; mi++) {
            ldsm_x4(af0[mi], aS + mi * 16 * ASTRIDE);
            ldsm_x4(af1[mi], aS + mi * 16 * ASTRIDE + 32);
        }

#pragma unroll
        for (int mi = 0; mi < 2; mi++)
#pragma unroll
            for (int ni = 0; ni < NI; ni++) {
                mma_f16(acc[mi][ni], af0[mi], bq[ni].x, bq[ni].y);
                mma_f16(acc[mi][ni], af1[mi], bq[ni].z, bq[ni].w);
            }

        if (c + NS - 1 < NCH) {
            stage(c + NS - 1, sslot);
            if (++sslot == NS) sslot = 0;
        }
        if (++st == NS) st = 0;
    }

    if (EPI == 0) {
        if (tid < BN) { cs[tid] = 0.0f; cq[tid] = 0.0f; }
        __syncthreads();
    }
    if (EPI == 3) {
        if (tid < BN) {
            int idxc = d * 256 + bn + tid;
            float mean = sums[idxc] * (1.0f / BSZ);
            float var  = sums[DNUM * 256 + idxc] * (1.0f / BSZ) - mean * mean;
            float sc   = bng[d * N + bn + tid] * rsqrtf(var + 1e-5f);
            cs[tid] = sc;
            cq[tid] = bnb[d * N + bn + tid] - mean * sc;
        }
        __syncthreads();
    }

    float colS[NI][2] = {}, colQ[NI][2] = {};

#pragma unroll
    for (int mi = 0; mi < 2; mi++) {
        int r0 = wm * 32 + mi * 16 + gid;
#pragma unroll
        for (int ni = 0; ni < NI; ni++) {
            int col = wn * WN + ni * 8 + 2 * tig;
            float b0 = bias[d * N + bn + col];
            float b1 = bias[d * N + bn + col + 1];
            float v0 = acc[mi][ni][0] + b0;
            float v1 = acc[mi][ni][1] + b1;
            float v2 = acc[mi][ni][2] + b0;
            float v3 = acc[mi][ni][3] + b1;
            if (EPI == 0) {
                colS[ni][0] += v0 + v2;      colS[ni][1] += v1 + v3;
                colQ[ni][0] += v0 * v0 + v2 * v2;
                colQ[ni][1] += v1 * v1 + v3 * v3;
                *(float2*)(Cfd + (size_t)r0 * N + col)       = make_float2(v0, v1);
                *(float2*)(Cfd + (size_t)(r0 + 8) * N + col) = make_float2(v2, v3);
            }
            if (EPI == 1) {
                *(__half2*)(Chd + (size_t)r0 * N + col) =
                    __floats2half2_rn(fmaxf(v0, 0.0f), fmaxf(v1, 0.0f));
                *(__half2*)(Chd + (size_t)(r0 + 8) * N + col) =
                    __floats2half2_rn(fmaxf(v2, 0.0f), fmaxf(v3, 0.0f));
            }
            if (EPI == 3) {
                float g0 = 2.0f / (1.0f + expf(-v0));
                float g1 = 2.0f / (1.0f + expf(-v1));
                float g2 = 2.0f / (1.0f + expf(-v2));
                float g3 = 2.0f / (1.0f + expf(-v3));
                float2 h01 = *(float2*)(Cfd + (size_t)r0 * N + col);
                float2 h23 = *(float2*)(Cfd + (size_t)(r0 + 8) * N + col);
                float sc0 = cs[col], sh0 = cq[col];
                float sc1 = cs[col + 1], sh1 = cq[col + 1];
                *(__half2*)(Chd + (size_t)r0 * N + col) = __floats2half2_rn(
                    fmaxf(h01.x * sc0 + sh0, 0.0f) * g0,
                    fmaxf(h01.y * sc1 + sh1, 0.0f) * g1);
                *(__half2*)(Chd + (size_t)(r0 + 8) * N + col) = __floats2half2_rn(
                    fmaxf(h23.x * sc0 + sh0, 0.0f) * g2,
                    fmaxf(h23.y * sc1 + sh1, 0.0f) * g3);
            }
        }
    }

    if (EPI == 0) {
#pragma unroll
        for (int ni = 0; ni < NI; ni++)
#pragma unroll
            for (int c2 = 0; c2 < 2; c2++) {
                float sv = colS[ni][c2], qv = colQ[ni][c2];
                sv += __shfl_xor_sync(0xffffffffu, sv, 16);
                sv += __shfl_xor_sync(0xffffffffu, sv, 8);
                sv += __shfl_xor_sync(0xffffffffu, sv, 4);
                qv += __shfl_xor_sync(0xffffffffu, qv, 16);
                qv += __shfl_xor_sync(0xffffffffu, qv, 8);
                qv += __shfl_xor_sync(0xffffffffu, qv, 4);
                if (gid == 0) {
                    int c = wn * WN + ni * 8 + 2 * tig + c2;
                    atomicAdd(&cs[c], sv);
                    atomicAdd(&cq[c], qv);
                }
            }
        __syncthreads();
        if (tid < BN) {
            atomicAdd(&sums[d * 256 + bn + tid], cs[tid]);
            atomicAdd(&sums[DNUM * 256 + d * 256 + bn + tid], cq[tid]);
        }
    }
}

// ------------------------- final head -----------------------------------
__global__ void final_kernel(const __half* __restrict__ H,
                             const int* __restrict__ dom,
                             const float* __restrict__ finW,
                             const float* __restrict__ finb,
                             float* __restrict__ out) {
    int warp = (blockIdx.x * blockDim.x + threadIdx.x) >> 5;
    int lane = threadIdx.x & 31;
    if (warp >= BSZ) return;
    int d = dom[warp];
    const __half* h = H + ((size_t)d * BSZ + warp) * 64;
    const float* w = finW + d * 64;
    float s = __half2float(h[lane]) * w[lane] + __half2float(h[lane + 32]) * w[lane + 32];
#pragma unroll
    for (int o = 16; o > 0; o >>= 1) s += __shfl_down_sync(0xffffffffu, s, o);
    if (lane == 0) out[warp] = 1.0f / (1.0f + expf(-(s + finb[d])));
}

// ------------------------- dispatch helper ------------------------------
template <int EPI>
static void launch_gemm(cudaStream_t st, const __half* A, size_t aStride,
                        const __half* Wp, const float* b, float* Cf, __half* Ch,
                        float* sums, const float* bng, const float* bnb, int K, int N) {
    if (N >= 128) {
        constexpr int SM = 4 * (128 * 80 + 128 * 64);    // 73728
        cudaFuncSetAttribute(gemm_tc<128, EPI>, cudaFuncAttributeMaxDynamicSharedMemorySize, SM);
        dim3 grid(BSZ / 128, N / 128, DNUM);
        gemm_tc<128, EPI><<<grid, 256, SM, st>>>(A, aStride, Wp, b, Cf, Ch, sums, bng, bnb, K, N);
    } else {
        constexpr int SM = 4 * (128 * 80 + 64 * 64);     // 57344
        cudaFuncSetAttribute(gemm_tc<64, EPI>, cudaFuncAttributeMaxDynamicSharedMemorySize, SM);
        dim3 grid(BSZ / 128, N / 64, DNUM);
        gemm_tc<64, EPI><<<grid, 256, SM, st>>>(A, aStride, Wp, b, Cf, Ch, sums, bng, bnb, K, N);
    }
}

// ------------------------- launch --------------------------------------
extern "C" void kernel_launch(void* const* d_in, const int* in_sizes, int n_in,
                              void* d_out, int out_size) {
    const int*   id_idx    = (const int*)d_in[0];
    const int*   agn_idx   = (const int*)d_in[1];
    const int*   domain_id = (const int*)d_in[2];
    const float* id_tab    = (const float*)d_in[3];
    const float* agn_tab   = (const float*)d_in[4];
    const float* mlp_W[3]  = {(const float*)d_in[5],  (const float*)d_in[13], (const float*)d_in[21]};
    const float* mlp_b[3]  = {(const float*)d_in[6],  (const float*)d_in[14], (const float*)d_in[22]};
    const float* bn_g[3]   = {(const float*)d_in[7],  (const float*)d_in[15], (const float*)d_in[23]};
    const float* bn_b[3]   = {(const float*)d_in[8],  (const float*)d_in[16], (const float*)d_in[24]};
    const float* gW1[3]    = {(const float*)d_in[9],  (const float*)d_in[17], (const float*)d_in[25]};
    const float* gb1[3]    = {(const float*)d_in[10], (const float*)d_in[18], (const float*)d_in[26]};
    const float* gW2[3]    = {(const float*)d_in[11], (const float*)d_in[19], (const float*)d_in[27]};
    const float* gb2[3]    = {(const float*)d_in[12], (const float*)d_in[20], (const float*)d_in[28]};
    const float* finW      = (const float*)d_in[29];
    const float* finb      = (const float*)d_in[30];
    float*       out       = (float*)d_out;

    __half *p_gate_h, *p_g1h, *p_hh, *p_w;
    float *p_hpre, *p_sums;
    cudaGetSymbolAddress((void**)&p_gate_h, g_gate_h);
    cudaGetSymbolAddress((void**)&p_g1h, g_g1h);
    cudaGetSymbolAddress((void**)&p_hh, g_hh);
    cudaGetSymbolAddress((void**)&p_hpre, g_hpre);
    cudaGetSymbolAddress((void**)&p_sums, g_sums3);
    cudaGetSymbolAddress((void**)&p_w, g_wh);

    // one-time host objects (no device memory involved)
    static cudaStream_t s1 = nullptr;
    static cudaEvent_t evStart, evEmbed, evPrep, evG1[3];
    if (!s1) {
        cudaStreamCreateWithFlags(&s1, cudaStreamNonBlocking);
        cudaEventCreateWithFlags(&evStart, cudaEventDisableTiming);
        cudaEventCreateWithFlags(&evEmbed, cudaEventDisableTiming);
        cudaEventCreateWithFlags(&evPrep, cudaEventDisableTiming);
        for (int i = 0; i < 3; i++) cudaEventCreateWithFlags(&evG1[i], cudaEventDisableTiming);
    }

    const int dims[4] = {256, 256, 128, 64};

    // packed fp16 weights
    __half* rW1[3]; __half* rW2[3]; __half* rWm[3];
    size_t off = 0;
    TArgs ta;
    int segi = 0, maxn = 0;
    for (int i = 0; i < 3; i++) {
        int N = dims[i + 1];
        rW1[i] = p_w + off;
        ta.seg[segi++] = {gW1[i], p_w + off, IND, N, DNUM * IND * N};           off += (size_t)DNUM * IND * N;
        rW2[i] = p_w + off;
        ta.seg[segi++] = {gW2[i], p_w + off, N, N, DNUM * N * N};               off += (size_t)DNUM * N * N;
        rWm[i] = p_w + off;
        ta.seg[segi++] = {mlp_W[i], p_w + off, dims[i], N, DNUM * dims[i] * N}; off += (size_t)DNUM * dims[i] * N;
    }
    for (int s = 0; s < 9; s++) if (ta.seg[s].total > maxn) maxn = ta.seg[s].total;

    // per-layer g1 buffers
    __half* g1buf[3];
    size_t goff = 0;
    for (int i = 0; i < 3; i++) {
        g1buf[i] = p_g1h + goff;
        goff += (size_t)DNUM * BSZ * dims[i + 1];
    }

    // ---- fork -----------------------------------------------------------
    cudaEventRecord(evStart, 0);
    cudaStreamWaitEvent(s1, evStart, 0);

    // s1: prep -> (evPrep) -> wait embed -> gW1 x3
    dim3 rg((maxn + 255) / 256, 9);
    prep_weights<<<rg, 256, 0, s1>>>(ta);
    cudaEventRecord(evPrep, s1);

    // s0: embed
    embed_kernel<<<(BSZ * 64 + 255) / 256, 256>>>(id_idx, agn_idx, id_tab, agn_tab);
    cudaEventRecord(evEmbed, 0);
    cudaStreamWaitEvent(s1, evEmbed, 0);

    for (int i = 0; i < 3; i++) {
        launch_gemm<1>(s1, p_gate_h, 0, rW1[i], gb1[i], nullptr, g1buf[i],
                       nullptr, nullptr, nullptr, IND, dims[i + 1]);
        cudaEventRecord(evG1[i], s1);
    }

    // ---- main stream: (wait prep) -> mlp0 -> [wait g1_i] gW2_i ... ------
    cudaStreamWaitEvent(0, evPrep, 0);

    const __half* hprev = nullptr;
    for (int i = 0; i < 3; i++) {
        int Kmlp = dims[i];
        int N    = dims[i + 1];
        float* sums = p_sums + (size_t)i * 2 * DNUM * 256;

        if (i == 0)
            launch_gemm<0>(0, p_gate_h, 0, rWm[i], mlp_b[i], p_hpre, nullptr,
                           sums, nullptr, nullptr, IND, N);
        else
            launch_gemm<0>(0, hprev, (size_t)BSZ * Kmlp, rWm[i], mlp_b[i], p_hpre, nullptr,
                           sums, nullptr, nullptr, Kmlp, N);

        cudaStreamWaitEvent(0, evG1[i], 0);
        launch_gemm<3>(0, g1buf[i], (size_t)BSZ * N, rW2[i], gb2[i], p_hpre, p_hh,
                       sums, bn_g[i], bn_b[i], N, N);

        hprev = p_hh;
    }

    final_kernel<<<BSZ / 8, 256>>>(hprev, domain_id, finW, finb, out);
}